// round 2
// baseline (speedup 1.0000x reference)
#include <cuda_runtime.h>
#include <math.h>

#define NTOK 4096
#define DM   512
#define EX   32
#define HH   128
#define TOPK 4
#define NK   (NTOK*TOPK)

// ---- scratch (device globals; no allocation allowed) ----
__device__ int   g_counts[EX];
__device__ int   g_offsets[EX + 1];
__device__ int   g_cursor[EX];
__device__ int   g_route_e[NK];
__device__ float g_route_g[NK];
__device__ int   g_perm_nk[NK];   // n*4+k, grouped by expert
__device__ float g_perm_g[NK];
__device__ float g_buf[NK * DM];  // 32 MB partial outputs, indexed by (n*4+k)

// ---------------- zero counts ----------------
__global__ void k_zero() {
    int t = threadIdx.x;
    if (t < EX) g_counts[t] = 0;
}

// ---------------- routing: warp per token ----------------
__global__ void __launch_bounds__(256) k_route(const float* __restrict__ x,
                                               const float* __restrict__ sel) {
    int warp = (blockIdx.x * blockDim.x + threadIdx.x) >> 5;
    int lane = threadIdx.x & 31;
    if (warp >= NTOK) return;
    int n = warp;

    float acc[EX];
#pragma unroll
    for (int e = 0; e < EX; e++) acc[e] = 0.f;

    const float* xr = x + n * DM;
#pragma unroll
    for (int i = 0; i < DM / 32; i++) {
        float xv = xr[i * 32 + lane];
#pragma unroll
        for (int e = 0; e < EX; e++)
            acc[e] += xv * sel[e * DM + i * 32 + lane];
    }
    // butterfly reduce all 32 accumulators
#pragma unroll
    for (int off = 16; off; off >>= 1) {
#pragma unroll
        for (int e = 0; e < EX; e++)
            acc[e] += __shfl_xor_sync(0xffffffffu, acc[e], off);
    }

    if (lane == 0) {
        float s[EX];
#pragma unroll
        for (int e = 0; e < EX; e++) s[e] = acc[e];
        for (int k = 0; k < TOPK; k++) {
            float best = -INFINITY;
            int bi = -1;
#pragma unroll
            for (int e = 0; e < EX; e++) {
                if (s[e] > best) { best = s[e]; bi = e; }
            }
#pragma unroll
            for (int e = 0; e < EX; e++) {
                if (e == bi) s[e] = -INFINITY;
            }
            float gate = 1.f / (1.f + expf(-best));
            g_route_e[n * TOPK + k] = bi;
            g_route_g[n * TOPK + k] = gate;
            atomicAdd(&g_counts[bi], 1);
        }
    }
}

// ---------------- scan: 1 warp prefix over 32 experts ----------------
__global__ void k_scan() {
    int lane = threadIdx.x;
    int c = (lane < EX) ? g_counts[lane] : 0;
    int s = c;
#pragma unroll
    for (int off = 1; off < 32; off <<= 1) {
        int v = __shfl_up_sync(0xffffffffu, s, off);
        if (lane >= off) s += v;
    }
    int ex = s - c;  // exclusive
    if (lane < EX) { g_offsets[lane] = ex; g_cursor[lane] = ex; }
    if (lane == EX - 1) g_offsets[EX] = s;
}

// ---------------- fill per-expert token lists ----------------
__global__ void k_fill() {
    int t = blockIdx.x * blockDim.x + threadIdx.x;
    if (t < NK) {
        int e = g_route_e[t];
        int p = atomicAdd(&g_cursor[e], 1);
        g_perm_nk[p] = t;
        g_perm_g[p]  = g_route_g[t];
    }
}

// ---------------- expert MLP tile: 64 tokens x one expert ----------------
#define TM 64
#define KT 16

__global__ void __launch_bounds__(256) k_expert(const float* __restrict__ x,
                                                const float* __restrict__ w1,
                                                const float* __restrict__ w2) {
    __shared__ float Xs[TM][KT];     // 4 KB
    __shared__ float Ws[KT][HH];     // 8 KB (W1 tile, reused for W2 tile)
    __shared__ float Hs[TM][HH];     // 32 KB
    __shared__ int   nk_sh[TM];
    __shared__ float g_sh[TM];

    int e    = blockIdx.y;
    int base = g_offsets[e] + blockIdx.x * TM;
    int end  = g_offsets[e + 1];
    if (base >= end) return;
    int cnt = min(TM, end - base);

    int tid  = threadIdx.x;
    int tcol = tid & 31;   // 32 col-groups of 4
    int trow = tid >> 5;   // 8 row-groups, rows trow + 8*i

    if (tid < TM) {
        if (tid < cnt) { nk_sh[tid] = g_perm_nk[base + tid]; g_sh[tid] = g_perm_g[base + tid]; }
        else           { nk_sh[tid] = 0;                     g_sh[tid] = 0.f; }
    }
    __syncthreads();

    const float* w1e = w1 + e * DM * HH;
    const float* w2e = w2 + e * HH * DM;

    // ---- phase 1: H = relu(Xg * W1) * gate  ([64,512]x[512,128]) ----
    float acc[8][4];
#pragma unroll
    for (int i = 0; i < 8; i++)
#pragma unroll
        for (int j = 0; j < 4; j++) acc[i][j] = 0.f;

    for (int k0 = 0; k0 < DM; k0 += KT) {
        {   // load Xs: 64x16, 4 floats/thread (gathered rows)
            int q = tid * 4;
            int r = q / KT;
            int c = q % KT;
            int n = nk_sh[r] >> 2;
            *(float4*)&Xs[r][c] = *(const float4*)(x + n * DM + k0 + c);
        }
        {   // load W1 tile: 16x128, 8 floats/thread
            int q = tid * 8;
            int r = q / HH;
            int c = q % HH;
            const float4* src = (const float4*)(w1e + (k0 + r) * HH + c);
            *(float4*)&Ws[r][c]     = src[0];
            *(float4*)&Ws[r][c + 4] = src[1];
        }
        __syncthreads();
#pragma unroll
        for (int kk = 0; kk < KT; kk++) {
            float4 b = *(float4*)&Ws[kk][tcol * 4];
#pragma unroll
            for (int i = 0; i < 8; i++) {
                float a = Xs[trow + 8 * i][kk];
                acc[i][0] += a * b.x;
                acc[i][1] += a * b.y;
                acc[i][2] += a * b.z;
                acc[i][3] += a * b.w;
            }
        }
        __syncthreads();
    }
    // relu * gate -> Hs
#pragma unroll
    for (int i = 0; i < 8; i++) {
        int r = trow + 8 * i;
        float g = g_sh[r];
        float4 h;
        h.x = fmaxf(acc[i][0], 0.f) * g;
        h.y = fmaxf(acc[i][1], 0.f) * g;
        h.z = fmaxf(acc[i][2], 0.f) * g;
        h.w = fmaxf(acc[i][3], 0.f) * g;
        *(float4*)&Hs[r][tcol * 4] = h;
    }
    __syncthreads();

    // ---- phase 2: Y = Hs * W2  ([64,128]x[128,512]), 128-col chunks ----
    for (int v0 = 0; v0 < DM; v0 += 128) {
        float acc2[8][4];
#pragma unroll
        for (int i = 0; i < 8; i++)
#pragma unroll
            for (int j = 0; j < 4; j++) acc2[i][j] = 0.f;

        for (int k0 = 0; k0 < HH; k0 += KT) {
            {   // load W2 tile: 16x128 (cols v0..v0+127)
                int q = tid * 8;
                int r = q / 128;
                int c = q % 128;
                const float4* src = (const float4*)(w2e + (k0 + r) * DM + v0 + c);
                *(float4*)&Ws[r][c]     = src[0];
                *(float4*)&Ws[r][c + 4] = src[1];
            }
            __syncthreads();
#pragma unroll
            for (int kk = 0; kk < KT; kk++) {
                float4 b = *(float4*)&Ws[kk][tcol * 4];
#pragma unroll
                for (int i = 0; i < 8; i++) {
                    float a = Hs[trow + 8 * i][k0 + kk];
                    acc2[i][0] += a * b.x;
                    acc2[i][1] += a * b.y;
                    acc2[i][2] += a * b.z;
                    acc2[i][3] += a * b.w;
                }
            }
            __syncthreads();
        }
        // store partials to (n,k)-indexed buffer (deterministic, no atomics)
#pragma unroll
        for (int i = 0; i < 8; i++) {
            int r = trow + 8 * i;
            if (r < cnt) {
                int nk = nk_sh[r];
                float4 o;
                o.x = acc2[i][0]; o.y = acc2[i][1]; o.z = acc2[i][2]; o.w = acc2[i][3];
                *(float4*)&g_buf[nk * DM + v0 + tcol * 4] = o;
            }
        }
    }
}

// ---------------- reduce 4 partials per token ----------------
__global__ void __launch_bounds__(256) k_reduce(float* __restrict__ y) {
    int t = blockIdx.x * blockDim.x + threadIdx.x;  // over N*D/4
    if (t >= NTOK * DM / 4) return;
    int n  = t / (DM / 4);
    int v4 = t % (DM / 4);
    const float4* b = (const float4*)g_buf;
    float4 r0 = b[(size_t)(n * 4 + 0) * (DM / 4) + v4];
    float4 r1 = b[(size_t)(n * 4 + 1) * (DM / 4) + v4];
    float4 r2 = b[(size_t)(n * 4 + 2) * (DM / 4) + v4];
    float4 r3 = b[(size_t)(n * 4 + 3) * (DM / 4) + v4];
    float4 o;
    o.x = (r0.x + r1.x) + (r2.x + r3.x);
    o.y = (r0.y + r1.y) + (r2.y + r3.y);
    o.z = (r0.z + r1.z) + (r2.z + r3.z);
    o.w = (r0.w + r1.w) + (r2.w + r3.w);
    ((float4*)y)[t] = o;
}

extern "C" void kernel_launch(void* const* d_in, const int* in_sizes, int n_in,
                              void* d_out, int out_size) {
    const float* x   = (const float*)d_in[0];
    const float* sel = (const float*)d_in[1];
    const float* w1  = (const float*)d_in[2];
    const float* w2  = (const float*)d_in[3];
    float* y = (float*)d_out;

    k_zero<<<1, 32>>>();
    k_route<<<NTOK / 8, 256>>>(x, sel);
    k_scan<<<1, 32>>>();
    k_fill<<<NK / 256, 256>>>();
    dim3 grid(TM, EX);  // 64 tiles max (expert could own all 4096 tokens) x 32 experts
    k_expert<<<grid, 256>>>(x, w1, w2);
    k_reduce<<<(NTOK * DM / 4) / 256, 256>>>(y);
}

// round 4
// speedup vs baseline: 1.5675x; 1.5675x over previous
#include <cuda_runtime.h>
#include <cuda_bf16.h>
#include <math.h>
#include <stdint.h>

#define NTOK 4096
#define DM   512
#define EX   32
#define HH   128
#define TOPK 4
#define NK   (NTOK*TOPK)
#define MT   128   // token tile

// ---------------- device scratch (no allocs allowed) ----------------
__device__ int   g_counts[EX];
__device__ int   g_offsets[EX + 1];
__device__ int   g_cursor[EX];
__device__ int   g_route_e[NK];
__device__ float g_route_g[NK];
__device__ int   g_perm_nk[NK];
__device__ float g_perm_g[NK];
__device__ float g_scores[NTOK * EX];
__device__ float g_buf[NK * DM];                                     // 32 MB partials
__device__ __nv_bfloat16 g_xhi[NTOK * DM], g_xlo[NTOK * DM];         // [N,D]
__device__ __nv_bfloat16 g_w1hi[EX * HH * DM], g_w1lo[EX * HH * DM]; // [E,H,D] (W1^T)
__device__ __nv_bfloat16 g_w2hi[EX * DM * HH], g_w2lo[EX * DM * HH]; // [E,D,H] (W2^T)

// ---------------- helpers ----------------
__device__ __forceinline__ uint32_t smem_u32(const void* p) {
    uint32_t a;
    asm("{ .reg .u64 t; cvta.to.shared.u64 t, %1; cvt.u32.u64 %0, t; }" : "=r"(a) : "l"(p));
    return a;
}

__device__ __forceinline__ void ldm_x4(uint32_t* d, uint32_t addr) {
    asm volatile("ldmatrix.sync.aligned.m8n8.x4.shared.b16 {%0,%1,%2,%3}, [%4];"
                 : "=r"(d[0]), "=r"(d[1]), "=r"(d[2]), "=r"(d[3]) : "r"(addr));
}

__device__ __forceinline__ void mma_bf16(float* c, const uint32_t* a, uint32_t b0, uint32_t b1) {
    asm volatile(
        "mma.sync.aligned.m16n8k16.row.col.f32.bf16.bf16.f32 "
        "{%0,%1,%2,%3}, {%4,%5,%6,%7}, {%8,%9}, {%0,%1,%2,%3};"
        : "+f"(c[0]), "+f"(c[1]), "+f"(c[2]), "+f"(c[3])
        : "r"(a[0]), "r"(a[1]), "r"(a[2]), "r"(a[3]), "r"(b0), "r"(b1));
}

// ldmatrix lane address for A-style 16x16 frag (row-major [m][k], stride in bf16)
__device__ __forceinline__ uint32_t a_addr(uint32_t base, int stride, int m0, int k0, int lane) {
    int q = lane >> 3, r = lane & 7;
    int row = m0 + ((q & 1) << 3) + r;
    int col = k0 + ((q >> 1) << 3);
    return base + (uint32_t)(row * stride + col) * 2;
}
// ldmatrix lane address for B-style n16xk16 group (row-major [n][k]); regs 0,1 -> n-tile n0, regs 2,3 -> n0+8
__device__ __forceinline__ uint32_t b_addr(uint32_t base, int stride, int n0, int k0, int lane) {
    int q = lane >> 3, r = lane & 7;
    int row = n0 + ((q >> 1) << 3) + r;
    int col = k0 + ((q & 1) << 3);
    return base + (uint32_t)(row * stride + col) * 2;
}

// ---------------- small kernels ----------------
__global__ void k_zero() {
    if (threadIdx.x < EX) g_counts[threadIdx.x] = 0;
}

__global__ void __launch_bounds__(256) k_cvt_x(const float* __restrict__ x) {
    int i = (blockIdx.x * 256 + threadIdx.x) * 4;
    float4 v = *(const float4*)(x + i);
    __nv_bfloat16 h0 = __float2bfloat16(v.x), h1 = __float2bfloat16(v.y);
    __nv_bfloat16 h2 = __float2bfloat16(v.z), h3 = __float2bfloat16(v.w);
    __nv_bfloat162 a, b;
    a.x = h0; a.y = h1; b.x = h2; b.y = h3;
    *(__nv_bfloat162*)(g_xhi + i) = a;
    *(__nv_bfloat162*)(g_xhi + i + 2) = b;
    a.x = __float2bfloat16(v.x - __bfloat162float(h0));
    a.y = __float2bfloat16(v.y - __bfloat162float(h1));
    b.x = __float2bfloat16(v.z - __bfloat162float(h2));
    b.y = __float2bfloat16(v.w - __bfloat162float(h3));
    *(__nv_bfloat162*)(g_xlo + i) = a;
    *(__nv_bfloat162*)(g_xlo + i + 2) = b;
}

// transpose [R,C] -> [C,R] per expert with hi/lo split. which: 0 = w1, 1 = w2
__global__ void __launch_bounds__(256) k_cvt_w(const float* __restrict__ src, int which,
                                               int R, int C) {
    __shared__ float t[32][33];
    int e = blockIdx.z;
    int r0 = blockIdx.x * 32, c0 = blockIdx.y * 32;
    int tx = threadIdx.x & 31, ty = threadIdx.x >> 5;
    const float* s = src + (size_t)e * R * C;
#pragma unroll
    for (int j = 0; j < 4; j++) {
        int r = r0 + ty + 8 * j;
        t[ty + 8 * j][tx] = s[(size_t)r * C + c0 + tx];
    }
    __syncthreads();
    __nv_bfloat16* dh = which ? g_w2hi : g_w1hi;
    __nv_bfloat16* dl = which ? g_w2lo : g_w1lo;
    size_t eb = (size_t)e * R * C;
#pragma unroll
    for (int j = 0; j < 4; j++) {
        int c = c0 + ty + 8 * j;
        int r = r0 + tx;
        float v = t[tx][ty + 8 * j];
        __nv_bfloat16 h = __float2bfloat16(v);
        dh[eb + (size_t)c * R + r] = h;
        dl[eb + (size_t)c * R + r] = __float2bfloat16(v - __bfloat162float(h));
    }
}

// S[4096,32] = X * sel^T (tiny fp32 GEMM)
__global__ void __launch_bounds__(256) k_score(const float* __restrict__ x,
                                               const float* __restrict__ sel) {
    __shared__ float Xs[128][36];
    __shared__ float Bs[32][36];
    int tid = threadIdx.x;
    int n0 = blockIdx.x * 128;
    int trow = tid >> 3;
    int tc = (tid & 7) * 4;
    float acc[4][4];
#pragma unroll
    for (int i = 0; i < 4; i++)
#pragma unroll
        for (int j = 0; j < 4; j++) acc[i][j] = 0.f;

    for (int k0 = 0; k0 < DM; k0 += 32) {
#pragma unroll
        for (int j = 0; j < 4; j++) {
            int u = tid + 256 * j;
            int r = u >> 3, c = (u & 7) * 4;
            *(float4*)&Xs[r][c] = *(const float4*)(x + (size_t)(n0 + r) * DM + k0 + c);
        }
        {
            int e = tid >> 3, kk = (tid & 7) * 4;
            float4 v = *(const float4*)(sel + (size_t)e * DM + k0 + kk);
            Bs[kk][e] = v.x; Bs[kk + 1][e] = v.y; Bs[kk + 2][e] = v.z; Bs[kk + 3][e] = v.w;
        }
        __syncthreads();
#pragma unroll
        for (int kk = 0; kk < 32; kk++) {
            float4 b = *(float4*)&Bs[kk][tc];
#pragma unroll
            for (int i = 0; i < 4; i++) {
                float a = Xs[trow + 32 * i][kk];
                acc[i][0] += a * b.x; acc[i][1] += a * b.y;
                acc[i][2] += a * b.z; acc[i][3] += a * b.w;
            }
        }
        __syncthreads();
    }
#pragma unroll
    for (int i = 0; i < 4; i++)
        *(float4*)&g_scores[(size_t)(n0 + trow + 32 * i) * EX + tc] =
            make_float4(acc[i][0], acc[i][1], acc[i][2], acc[i][3]);
}

__global__ void __launch_bounds__(256) k_topk() {
    __shared__ int scnt[EX];
    int tid = threadIdx.x;
    if (tid < EX) scnt[tid] = 0;
    __syncthreads();
    int n = blockIdx.x * 256 + tid;
    float s[EX];
#pragma unroll
    for (int j = 0; j < EX / 4; j++) {
        float4 v = *(const float4*)&g_scores[(size_t)n * EX + j * 4];
        s[j * 4] = v.x; s[j * 4 + 1] = v.y; s[j * 4 + 2] = v.z; s[j * 4 + 3] = v.w;
    }
    for (int k = 0; k < TOPK; k++) {
        float best = -INFINITY; int bi = 0;
#pragma unroll
        for (int e = 0; e < EX; e++)
            if (s[e] > best) { best = s[e]; bi = e; }
        s[bi] = -INFINITY;
        g_route_e[n * TOPK + k] = bi;
        g_route_g[n * TOPK + k] = 1.f / (1.f + expf(-best));
        atomicAdd(&scnt[bi], 1);
    }
    __syncthreads();
    if (tid < EX && scnt[tid]) atomicAdd(&g_counts[tid], scnt[tid]);
}

__global__ void k_scan() {
    int lane = threadIdx.x;
    int c = (lane < EX) ? g_counts[lane] : 0;
    int sum = c;
#pragma unroll
    for (int off = 1; off < 32; off <<= 1) {
        int v = __shfl_up_sync(0xffffffffu, sum, off);
        if (lane >= off) sum += v;
    }
    int ex = sum - c;
    if (lane < EX) { g_offsets[lane] = ex; g_cursor[lane] = ex; }
    if (lane == EX - 1) g_offsets[EX] = sum;
}

__global__ void __launch_bounds__(256) k_fill() {
    __shared__ int scnt[EX], sbase[EX];
    int tid = threadIdx.x;
    if (tid < EX) scnt[tid] = 0;
    __syncthreads();
    int t = blockIdx.x * 256 + tid;
    int e = g_route_e[t];
    int lp = atomicAdd(&scnt[e], 1);
    __syncthreads();
    if (tid < EX) sbase[tid] = scnt[tid] ? atomicAdd(&g_cursor[tid], scnt[tid]) : 0;
    __syncthreads();
    int p = sbase[e] + lp;
    g_perm_nk[p] = t;
    g_perm_g[p] = g_route_g[t];
}

// ---------------- expert MLP via mma.sync bf16 hi/lo ----------------
#define AST 72     // smem row stride (bf16) for 64-col tiles
#define HST 136    // smem row stride (bf16) for 128-col tiles
#define OFF_A1HI 0
#define OFF_A1LO 18432
#define OFF_B1HI 36864
#define OFF_B1LO 55296
#define OFF_B2HI 0        // GEMM2 B tile reuses GEMM1 staging region
#define OFF_B2LO 34816
#define OFF_HHI  73728
#define OFF_HLO  108544
#define OFF_NK   143360
#define OFF_NROW 143872
#define OFF_GATE 144384
#define SMEM_EXPERT 144896

__global__ void __launch_bounds__(256, 1) k_expert() {
    extern __shared__ char sm[];
    int e    = blockIdx.y;
    int base = g_offsets[e] + blockIdx.x * MT;
    int end  = g_offsets[e + 1];
    if (base >= end) return;
    int cnt = min(MT, end - base);

    int tid = threadIdx.x, lane = tid & 31, wid = tid >> 5;
    int wm = wid & 3, wn = wid >> 2;         // 4x2 warp grid: 32-row x 64-col tiles
    uint32_t smb = smem_u32(sm);

    int*   nks   = (int*)(sm + OFF_NK);
    int*   nrow  = (int*)(sm + OFF_NROW);
    float* gates = (float*)(sm + OFF_GATE);
    if (tid < MT) {
        if (tid < cnt) {
            int nk = g_perm_nk[base + tid];
            nks[tid] = nk; nrow[tid] = nk >> 2; gates[tid] = g_perm_g[base + tid];
        } else {
            nks[tid] = 0; nrow[tid] = 0; gates[tid] = 0.f;
        }
    }
    __syncthreads();

    const __nv_bfloat16* w1h = g_w1hi + (size_t)e * HH * DM;
    const __nv_bfloat16* w1l = g_w1lo + (size_t)e * HH * DM;
    const __nv_bfloat16* w2h = g_w2hi + (size_t)e * DM * HH;
    const __nv_bfloat16* w2l = g_w2lo + (size_t)e * DM * HH;

    int g = lane >> 2, t4 = lane & 3;

    // ---- GEMM1: H128 = Xg[128,512] * W1[512,128], K chunks of 64 ----
    float c1[2][8][4];
#pragma unroll
    for (int mi = 0; mi < 2; mi++)
#pragma unroll
        for (int ni = 0; ni < 8; ni++)
#pragma unroll
            for (int j = 0; j < 4; j++) c1[mi][ni][j] = 0.f;

    for (int kc = 0; kc < 8; kc++) {
        int k0 = kc * 64;
#pragma unroll
        for (int i = 0; i < 4; i++) {        // A tiles: gathered token rows
            int u = tid + 256 * i;
            int r = u >> 3, c8 = (u & 7) * 8;
            size_t s = (size_t)nrow[r] * DM + k0 + c8;
            uint32_t o = (uint32_t)(r * AST + c8) * 2;
            *(uint4*)(sm + OFF_A1HI + o) = *(const uint4*)(g_xhi + s);
            *(uint4*)(sm + OFF_A1LO + o) = *(const uint4*)(g_xlo + s);
        }
#pragma unroll
        for (int i = 0; i < 4; i++) {        // B tiles: W1^T rows (h), k cols
            int u = tid + 256 * i;
            int r = u >> 3, c8 = (u & 7) * 8;
            size_t s = (size_t)r * DM + k0 + c8;
            uint32_t o = (uint32_t)(r * AST + c8) * 2;
            *(uint4*)(sm + OFF_B1HI + o) = *(const uint4*)(w1h + s);
            *(uint4*)(sm + OFF_B1LO + o) = *(const uint4*)(w1l + s);
        }
        __syncthreads();
#pragma unroll
        for (int ks = 0; ks < 4; ks++) {
            uint32_t ah[2][4], al[2][4];
#pragma unroll
            for (int mi = 0; mi < 2; mi++) {
                ldm_x4(ah[mi], a_addr(smb + OFF_A1HI, AST, wm * 32 + mi * 16, ks * 16, lane));
                ldm_x4(al[mi], a_addr(smb + OFF_A1LO, AST, wm * 32 + mi * 16, ks * 16, lane));
            }
            uint32_t bh[4][4], bl[4][4];
#pragma unroll
            for (int ng = 0; ng < 4; ng++) {
                ldm_x4(bh[ng], b_addr(smb + OFF_B1HI, AST, wn * 64 + ng * 16, ks * 16, lane));
                ldm_x4(bl[ng], b_addr(smb + OFF_B1LO, AST, wn * 64 + ng * 16, ks * 16, lane));
            }
#pragma unroll
            for (int mi = 0; mi < 2; mi++)
#pragma unroll
                for (int ni = 0; ni < 8; ni++) {
                    int ngp = ni >> 1, pr = (ni & 1) * 2;
                    mma_bf16(c1[mi][ni], ah[mi], bh[ngp][pr], bh[ngp][pr + 1]);
                    mma_bf16(c1[mi][ni], ah[mi], bl[ngp][pr], bl[ngp][pr + 1]);
                    mma_bf16(c1[mi][ni], al[mi], bh[ngp][pr], bh[ngp][pr + 1]);
                }
        }
        __syncthreads();
    }

    // ---- H = relu(D1)*gate -> bf16 hi/lo in SMEM ----
#pragma unroll
    for (int mi = 0; mi < 2; mi++) {
        int rA = wm * 32 + mi * 16 + g;
        float gA = gates[rA], gB = gates[rA + 8];
#pragma unroll
        for (int ni = 0; ni < 8; ni++) {
            int col = wn * 64 + ni * 8 + t4 * 2;
            float h0 = fmaxf(c1[mi][ni][0], 0.f) * gA;
            float h1 = fmaxf(c1[mi][ni][1], 0.f) * gA;
            float h2 = fmaxf(c1[mi][ni][2], 0.f) * gB;
            float h3 = fmaxf(c1[mi][ni][3], 0.f) * gB;
            __nv_bfloat162 vh, vl;
            vh.x = __float2bfloat16(h0); vh.y = __float2bfloat16(h1);
            vl.x = __float2bfloat16(h0 - __bfloat162float(vh.x));
            vl.y = __float2bfloat16(h1 - __bfloat162float(vh.y));
            *(__nv_bfloat162*)(sm + OFF_HHI + (uint32_t)(rA * HST + col) * 2) = vh;
            *(__nv_bfloat162*)(sm + OFF_HLO + (uint32_t)(rA * HST + col) * 2) = vl;
            vh.x = __float2bfloat16(h2); vh.y = __float2bfloat16(h3);
            vl.x = __float2bfloat16(h2 - __bfloat162float(vh.x));
            vl.y = __float2bfloat16(h3 - __bfloat162float(vh.y));
            *(__nv_bfloat162*)(sm + OFF_HHI + (uint32_t)((rA + 8) * HST + col) * 2) = vh;
            *(__nv_bfloat162*)(sm + OFF_HLO + (uint32_t)((rA + 8) * HST + col) * 2) = vl;
        }
    }
    __syncthreads();

    // ---- GEMM2: Y = H[128,128] * W2[128,512], per 128-col v chunk ----
    for (int v = 0; v < 4; v++) {
        int v0 = v * 128;
#pragma unroll
        for (int i = 0; i < 8; i++) {        // B tiles: W2^T rows (v0+d), 128 k cols
            int u = tid + 256 * i;
            int r = u >> 4, c8 = (u & 15) * 8;
            size_t s = (size_t)(v0 + r) * HH + c8;
            uint32_t o = (uint32_t)(r * HST + c8) * 2;
            *(uint4*)(sm + OFF_B2HI + o) = *(const uint4*)(w2h + s);
            *(uint4*)(sm + OFF_B2LO + o) = *(const uint4*)(w2l + s);
        }
        __syncthreads();

        float c2[2][8][4];
#pragma unroll
        for (int mi = 0; mi < 2; mi++)
#pragma unroll
            for (int ni = 0; ni < 8; ni++)
#pragma unroll
                for (int j = 0; j < 4; j++) c2[mi][ni][j] = 0.f;

#pragma unroll
        for (int ks = 0; ks < 8; ks++) {
            uint32_t ah[2][4], al[2][4];
#pragma unroll
            for (int mi = 0; mi < 2; mi++) {
                ldm_x4(ah[mi], a_addr(smb + OFF_HHI, HST, wm * 32 + mi * 16, ks * 16, lane));
                ldm_x4(al[mi], a_addr(smb + OFF_HLO, HST, wm * 32 + mi * 16, ks * 16, lane));
            }
            uint32_t bh[4][4], bl[4][4];
#pragma unroll
            for (int ng = 0; ng < 4; ng++) {
                ldm_x4(bh[ng], b_addr(smb + OFF_B2HI, HST, wn * 64 + ng * 16, ks * 16, lane));
                ldm_x4(bl[ng], b_addr(smb + OFF_B2LO, HST, wn * 64 + ng * 16, ks * 16, lane));
            }
#pragma unroll
            for (int mi = 0; mi < 2; mi++)
#pragma unroll
                for (int ni = 0; ni < 8; ni++) {
                    int ngp = ni >> 1, pr = (ni & 1) * 2;
                    mma_bf16(c2[mi][ni], ah[mi], bh[ngp][pr], bh[ngp][pr + 1]);
                    mma_bf16(c2[mi][ni], ah[mi], bl[ngp][pr], bl[ngp][pr + 1]);
                    mma_bf16(c2[mi][ni], al[mi], bh[ngp][pr], bh[ngp][pr + 1]);
                }
        }

        // store partials (deterministic, indexed by nk)
#pragma unroll
        for (int mi = 0; mi < 2; mi++) {
            int rA = wm * 32 + mi * 16 + g;
            int rB = rA + 8;
#pragma unroll
            for (int ni = 0; ni < 8; ni++) {
                int col = v0 + wn * 64 + ni * 8 + t4 * 2;
                if (rA < cnt) {
                    float2 o0; o0.x = c2[mi][ni][0]; o0.y = c2[mi][ni][1];
                    *(float2*)(g_buf + (size_t)nks[rA] * DM + col) = o0;
                }
                if (rB < cnt) {
                    float2 o1; o1.x = c2[mi][ni][2]; o1.y = c2[mi][ni][3];
                    *(float2*)(g_buf + (size_t)nks[rB] * DM + col) = o1;
                }
            }
        }
        __syncthreads();
    }
}

// ---------------- reduce 4 partials per token ----------------
__global__ void __launch_bounds__(256) k_reduce(float* __restrict__ y) {
    int t = blockIdx.x * 256 + threadIdx.x;
    int n  = t / (DM / 4);
    int v4 = t % (DM / 4);
    const float4* b = (const float4*)g_buf;
    float4 r0 = b[(size_t)(n * 4 + 0) * (DM / 4) + v4];
    float4 r1 = b[(size_t)(n * 4 + 1) * (DM / 4) + v4];
    float4 r2 = b[(size_t)(n * 4 + 2) * (DM / 4) + v4];
    float4 r3 = b[(size_t)(n * 4 + 3) * (DM / 4) + v4];
    float4 o;
    o.x = (r0.x + r1.x) + (r2.x + r3.x);
    o.y = (r0.y + r1.y) + (r2.y + r3.y);
    o.z = (r0.z + r1.z) + (r2.z + r3.z);
    o.w = (r0.w + r1.w) + (r2.w + r3.w);
    ((float4*)y)[t] = o;
}

extern "C" void kernel_launch(void* const* d_in, const int* in_sizes, int n_in,
                              void* d_out, int out_size) {
    const float* x   = (const float*)d_in[0];
    const float* sel = (const float*)d_in[1];
    const float* w1  = (const float*)d_in[2];
    const float* w2  = (const float*)d_in[3];
    float* y = (float*)d_out;

    cudaFuncSetAttribute(k_expert, cudaFuncAttributeMaxDynamicSharedMemorySize, SMEM_EXPERT);

    k_zero<<<1, 32>>>();
    k_cvt_x<<<NTOK * DM / 4 / 256, 256>>>(x);
    k_cvt_w<<<dim3(DM / 32, HH / 32, EX), 256>>>(w1, 0, DM, HH);   // -> [E,H,D]
    k_cvt_w<<<dim3(HH / 32, DM / 32, EX), 256>>>(w2, 1, HH, DM);   // -> [E,D,H]
    k_score<<<NTOK / 128, 256>>>(x, sel);
    k_topk<<<NTOK / 256, 256>>>();
    k_scan<<<1, 32>>>();
    k_fill<<<NK / 256, 256>>>();
    k_expert<<<dim3(32, EX), 256, SMEM_EXPERT>>>();
    k_reduce<<<NTOK * DM / 4 / 256, 256>>>(y);
}

// round 6
// speedup vs baseline: 1.6930x; 1.0801x over previous
#include <cuda_runtime.h>
#include <cuda_bf16.h>
#include <math.h>
#include <stdint.h>

#define NTOK 4096
#define DM   512
#define EX   32
#define HH   128
#define TOPK 4
#define NK   (NTOK*TOPK)
#define MT   64    // token tile

#define XN (NTOK*DM)       // 2097152
#define WN (EX*DM*HH)      // 2097152

// ---------------- device scratch (no allocs allowed) ----------------
__device__ int   g_counts[EX];
__device__ int   g_offsets[EX + 1];
__device__ int   g_cursor[EX];
__device__ int   g_route_e[NK];
__device__ float g_route_g[NK];
__device__ int   g_perm_nk[NK];
__device__ float g_perm_g[NK];
__device__ float g_buf[NK * DM];                                     // 32 MB partials
__device__ __nv_bfloat16 g_xhi[XN], g_xlo[XN];                       // [N,D]
__device__ __nv_bfloat16 g_w1hi[WN], g_w1lo[WN];                     // [E,D,H] natural
__device__ __nv_bfloat16 g_w2hi[WN], g_w2lo[WN];                     // [E,H,D] natural

// ---------------- helpers ----------------
__device__ __forceinline__ uint32_t smem_u32(const void* p) {
    uint32_t a;
    asm("{ .reg .u64 t; cvta.to.shared.u64 t, %1; cvt.u32.u64 %0, t; }" : "=r"(a) : "l"(p));
    return a;
}

__device__ __forceinline__ void ldm_x4(uint32_t* d, uint32_t addr) {
    asm volatile("ldmatrix.sync.aligned.m8n8.x4.shared.b16 {%0,%1,%2,%3}, [%4];"
                 : "=r"(d[0]), "=r"(d[1]), "=r"(d[2]), "=r"(d[3]) : "r"(addr));
}
__device__ __forceinline__ void ldm_x4t(uint32_t* d, uint32_t addr) {
    asm volatile("ldmatrix.sync.aligned.m8n8.x4.trans.shared.b16 {%0,%1,%2,%3}, [%4];"
                 : "=r"(d[0]), "=r"(d[1]), "=r"(d[2]), "=r"(d[3]) : "r"(addr));
}

__device__ __forceinline__ void mma_bf16(float* c, const uint32_t* a, uint32_t b0, uint32_t b1) {
    asm volatile(
        "mma.sync.aligned.m16n8k16.row.col.f32.bf16.bf16.f32 "
        "{%0,%1,%2,%3}, {%4,%5,%6,%7}, {%8,%9}, {%0,%1,%2,%3};"
        : "+f"(c[0]), "+f"(c[1]), "+f"(c[2]), "+f"(c[3])
        : "r"(a[0]), "r"(a[1]), "r"(a[2]), "r"(a[3]), "r"(b0), "r"(b1));
}

// A frag: row-major [m][k] smem, non-trans ldmatrix
__device__ __forceinline__ uint32_t a_addr(uint32_t base, int stride, int m0, int k0, int lane) {
    int q = lane >> 3, r = lane & 7;
    int row = m0 + ((q & 1) << 3) + r;
    int col = k0 + ((q >> 1) << 3);
    return base + (uint32_t)(row * stride + col) * 2;
}
// B frag: row-major [k][n] smem, TRANS ldmatrix. regs 0,1 -> n-tile n0; 2,3 -> n0+8
__device__ __forceinline__ uint32_t bt_addr(uint32_t base, int stride, int n0, int k0, int lane) {
    int q = lane >> 3, r = lane & 7;
    int row = k0 + ((q & 1) << 3) + r;
    int col = n0 + ((q >> 1) << 3);
    return base + (uint32_t)(row * stride + col) * 2;
}

// ---------------- fused fp32 -> bf16 hi/lo split of x, w1, w2 (+ counts zero) ----------------
__global__ void __launch_bounds__(256) k_cvt(const float* __restrict__ x,
                                             const float* __restrict__ w1,
                                             const float* __restrict__ w2) {
    if (blockIdx.x == 0 && threadIdx.x < EX) g_counts[threadIdx.x] = 0;
    int i = (blockIdx.x * 256 + threadIdx.x) * 4;
    const float* src;
    __nv_bfloat16 *dh, *dl;
    int off;
    if (i < XN)           { src = x;  dh = g_xhi;  dl = g_xlo;  off = i; }
    else if (i < XN + WN) { src = w1; dh = g_w1hi; dl = g_w1lo; off = i - XN; }
    else                  { src = w2; dh = g_w2hi; dl = g_w2lo; off = i - XN - WN; }
    float4 v = *(const float4*)(src + off);
    __nv_bfloat16 h0 = __float2bfloat16(v.x), h1 = __float2bfloat16(v.y);
    __nv_bfloat16 h2 = __float2bfloat16(v.z), h3 = __float2bfloat16(v.w);
    __nv_bfloat162 a, b;
    a.x = h0; a.y = h1; b.x = h2; b.y = h3;
    *(__nv_bfloat162*)(dh + off) = a;
    *(__nv_bfloat162*)(dh + off + 2) = b;
    a.x = __float2bfloat16(v.x - __bfloat162float(h0));
    a.y = __float2bfloat16(v.y - __bfloat162float(h1));
    b.x = __float2bfloat16(v.z - __bfloat162float(h2));
    b.y = __float2bfloat16(v.w - __bfloat162float(h3));
    *(__nv_bfloat162*)(dl + off) = a;
    *(__nv_bfloat162*)(dl + off + 2) = b;
}

// ---------------- fused routing: scores (128 tok x 32 exp per block) + top-4 ----------------
__global__ void __launch_bounds__(256) k_score(const float* __restrict__ x,
                                               const float* __restrict__ sel) {
    __shared__ float Xs[128][36];
    __shared__ float Bs[32][36];
    __shared__ float Ss[128][36];   // stride 36 floats = 144 B (16B-aligned rows)
    __shared__ int   scnt[EX];
    int tid = threadIdx.x;
    int n0 = blockIdx.x * 128;
    int trow = tid >> 3;
    int tc = (tid & 7) * 4;
    if (tid < EX) scnt[tid] = 0;
    float acc[4][4];
#pragma unroll
    for (int i = 0; i < 4; i++)
#pragma unroll
        for (int j = 0; j < 4; j++) acc[i][j] = 0.f;

    for (int k0 = 0; k0 < DM; k0 += 32) {
#pragma unroll
        for (int j = 0; j < 4; j++) {
            int u = tid + 256 * j;
            int r = u >> 3, c = (u & 7) * 4;
            *(float4*)&Xs[r][c] = *(const float4*)(x + (size_t)(n0 + r) * DM + k0 + c);
        }
        {
            int e = tid >> 3, kk = (tid & 7) * 4;
            float4 v = *(const float4*)(sel + (size_t)e * DM + k0 + kk);
            Bs[kk][e] = v.x; Bs[kk + 1][e] = v.y; Bs[kk + 2][e] = v.z; Bs[kk + 3][e] = v.w;
        }
        __syncthreads();
#pragma unroll
        for (int kk = 0; kk < 32; kk++) {
            float4 b = *(float4*)&Bs[kk][tc];
#pragma unroll
            for (int i = 0; i < 4; i++) {
                float a = Xs[trow + 32 * i][kk];
                acc[i][0] += a * b.x; acc[i][1] += a * b.y;
                acc[i][2] += a * b.z; acc[i][3] += a * b.w;
            }
        }
        __syncthreads();
    }
#pragma unroll
    for (int i = 0; i < 4; i++)
        *(float4*)&Ss[trow + 32 * i][tc] =
            make_float4(acc[i][0], acc[i][1], acc[i][2], acc[i][3]);
    __syncthreads();

    if (tid < 128) {
        int n = n0 + tid;
        float s[EX];
#pragma unroll
        for (int e = 0; e < EX; e++) s[e] = Ss[tid][e];
        for (int k = 0; k < TOPK; k++) {
            float best = -INFINITY; int bi = 0;
#pragma unroll
            for (int e = 0; e < EX; e++)
                if (s[e] > best) { best = s[e]; bi = e; }
            s[bi] = -INFINITY;
            g_route_e[n * TOPK + k] = bi;
            g_route_g[n * TOPK + k] = 1.f / (1.f + expf(-best));
            atomicAdd(&scnt[bi], 1);
        }
    }
    __syncthreads();
    if (tid < EX && scnt[tid]) atomicAdd(&g_counts[tid], scnt[tid]);
}

__global__ void k_scan() {
    int lane = threadIdx.x;
    int c = (lane < EX) ? g_counts[lane] : 0;
    int sum = c;
#pragma unroll
    for (int off = 1; off < 32; off <<= 1) {
        int v = __shfl_up_sync(0xffffffffu, sum, off);
        if (lane >= off) sum += v;
    }
    int ex = sum - c;
    if (lane < EX) { g_offsets[lane] = ex; g_cursor[lane] = ex; }
    if (lane == EX - 1) g_offsets[EX] = sum;
}

__global__ void __launch_bounds__(256) k_fill() {
    __shared__ int scnt[EX], sbase[EX];
    int tid = threadIdx.x;
    if (tid < EX) scnt[tid] = 0;
    __syncthreads();
    int t = blockIdx.x * 256 + tid;
    int e = g_route_e[t];
    int lp = atomicAdd(&scnt[e], 1);
    __syncthreads();
    if (tid < EX) sbase[tid] = scnt[tid] ? atomicAdd(&g_cursor[tid], scnt[tid]) : 0;
    __syncthreads();
    int p = sbase[e] + lp;
    g_perm_nk[p] = t;
    g_perm_g[p] = g_route_g[t];
}

// ---------------- expert MLP: MT=64 tile, mma.sync bf16 hi/lo, trans-B ----------------
#define AST 72     // [64m][64k] stride
#define HST 136    // 128-col stride
// byte offsets; GEMM1 staging aliases the B2 region
#define OFF_HHI  0
#define OFF_HLO  17408
#define OFF_B2HI 34816
#define OFF_B2LO 69632
#define OFF_A1HI 34816
#define OFF_A1LO 44032
#define OFF_B1HI 53248
#define OFF_B1LO 70656
#define OFF_NK   104448
#define OFF_NROW 104704
#define OFF_GATE 104960
#define SMEM_EXPERT 105216

__global__ void __launch_bounds__(256, 2) k_expert() {
    extern __shared__ char sm[];
    int e    = blockIdx.y;
    int base = g_offsets[e] + blockIdx.x * MT;
    int end  = g_offsets[e + 1];
    if (base >= end) return;
    int cnt = min(MT, end - base);

    int tid = threadIdx.x, lane = tid & 31, wid = tid >> 5;
    int wm = wid & 1, wn = wid >> 1;        // 2x4 warp grid: 32-row x 32-col tiles
    uint32_t smb = smem_u32(sm);

    int*   nks   = (int*)(sm + OFF_NK);
    int*   nrow  = (int*)(sm + OFF_NROW);
    float* gates = (float*)(sm + OFF_GATE);
    if (tid < MT) {
        if (tid < cnt) {
            int nk = g_perm_nk[base + tid];
            nks[tid] = nk; nrow[tid] = nk >> 2; gates[tid] = g_perm_g[base + tid];
        } else {
            nks[tid] = 0; nrow[tid] = 0; gates[tid] = 0.f;
        }
    }
    __syncthreads();

    const __nv_bfloat16* w1h = g_w1hi + (size_t)e * DM * HH;   // [D,H]
    const __nv_bfloat16* w1l = g_w1lo + (size_t)e * DM * HH;
    const __nv_bfloat16* w2h = g_w2hi + (size_t)e * HH * DM;   // [H,D]
    const __nv_bfloat16* w2l = g_w2lo + (size_t)e * HH * DM;

    int g = lane >> 2, t4 = lane & 3;

    // ---- GEMM1: H = Xg[64,512] * W1[512,128], K chunks of 64 ----
    float c1[2][4][4];
#pragma unroll
    for (int mi = 0; mi < 2; mi++)
#pragma unroll
        for (int ni = 0; ni < 4; ni++)
#pragma unroll
            for (int j = 0; j < 4; j++) c1[mi][ni][j] = 0.f;

    for (int kc = 0; kc < 8; kc++) {
        int k0 = kc * 64;
#pragma unroll
        for (int i = 0; i < 2; i++) {        // A [64m][64k], gathered rows
            int u = tid + 256 * i;
            int r = u >> 3, c8 = (u & 7) * 8;
            size_t s = (size_t)nrow[r] * DM + k0 + c8;
            uint32_t o = (uint32_t)(r * AST + c8) * 2;
            *(uint4*)(sm + OFF_A1HI + o) = *(const uint4*)(g_xhi + s);
            *(uint4*)(sm + OFF_A1LO + o) = *(const uint4*)(g_xlo + s);
        }
#pragma unroll
        for (int i = 0; i < 4; i++) {        // B1 [64k][128n] from w1 rows d=k0+r
            int u = tid + 256 * i;
            int r = u >> 4, c8 = (u & 15) * 8;
            size_t s = (size_t)(k0 + r) * HH + c8;
            uint32_t o = (uint32_t)(r * HST + c8) * 2;
            *(uint4*)(sm + OFF_B1HI + o) = *(const uint4*)(w1h + s);
            *(uint4*)(sm + OFF_B1LO + o) = *(const uint4*)(w1l + s);
        }
        __syncthreads();
#pragma unroll
        for (int ks = 0; ks < 4; ks++) {
            uint32_t ah[2][4], al[2][4];
#pragma unroll
            for (int mi = 0; mi < 2; mi++) {
                ldm_x4(ah[mi], a_addr(smb + OFF_A1HI, AST, wm * 32 + mi * 16, ks * 16, lane));
                ldm_x4(al[mi], a_addr(smb + OFF_A1LO, AST, wm * 32 + mi * 16, ks * 16, lane));
            }
            uint32_t bh[2][4], bl[2][4];
#pragma unroll
            for (int ng = 0; ng < 2; ng++) {
                ldm_x4t(bh[ng], bt_addr(smb + OFF_B1HI, HST, wn * 32 + ng * 16, ks * 16, lane));
                ldm_x4t(bl[ng], bt_addr(smb + OFF_B1LO, HST, wn * 32 + ng * 16, ks * 16, lane));
            }
#pragma unroll
            for (int mi = 0; mi < 2; mi++)
#pragma unroll
                for (int ni = 0; ni < 4; ni++) {
                    int ngp = ni >> 1, pr = (ni & 1) * 2;
                    mma_bf16(c1[mi][ni], ah[mi], bh[ngp][pr], bh[ngp][pr + 1]);
                    mma_bf16(c1[mi][ni], ah[mi], bl[ngp][pr], bl[ngp][pr + 1]);
                    mma_bf16(c1[mi][ni], al[mi], bh[ngp][pr], bh[ngp][pr + 1]);
                }
        }
        __syncthreads();
    }

    // ---- H = relu(.)*gate -> bf16 hi/lo SMEM [64m][128h] ----
#pragma unroll
    for (int mi = 0; mi < 2; mi++) {
        int rA = wm * 32 + mi * 16 + g;
        float gA = gates[rA], gB = gates[rA + 8];
#pragma unroll
        for (int ni = 0; ni < 4; ni++) {
            int col = wn * 32 + ni * 8 + t4 * 2;
            float h0 = fmaxf(c1[mi][ni][0], 0.f) * gA;
            float h1 = fmaxf(c1[mi][ni][1], 0.f) * gA;
            float h2 = fmaxf(c1[mi][ni][2], 0.f) * gB;
            float h3 = fmaxf(c1[mi][ni][3], 0.f) * gB;
            __nv_bfloat162 vh, vl;
            vh.x = __float2bfloat16(h0); vh.y = __float2bfloat16(h1);
            vl.x = __float2bfloat16(h0 - __bfloat162float(vh.x));
            vl.y = __float2bfloat16(h1 - __bfloat162float(vh.y));
            *(__nv_bfloat162*)(sm + OFF_HHI + (uint32_t)(rA * HST + col) * 2) = vh;
            *(__nv_bfloat162*)(sm + OFF_HLO + (uint32_t)(rA * HST + col) * 2) = vl;
            vh.x = __float2bfloat16(h2); vh.y = __float2bfloat16(h3);
            vl.x = __float2bfloat16(h2 - __bfloat162float(vh.x));
            vl.y = __float2bfloat16(h3 - __bfloat162float(vh.y));
            *(__nv_bfloat162*)(sm + OFF_HHI + (uint32_t)((rA + 8) * HST + col) * 2) = vh;
            *(__nv_bfloat162*)(sm + OFF_HLO + (uint32_t)((rA + 8) * HST + col) * 2) = vl;
        }
    }
    __syncthreads();

    // ---- GEMM2: Y = H[64,128] * W2[128,512] per 128-col chunk ----
    for (int v = 0; v < 4; v++) {
        int v0 = v * 128;
#pragma unroll
        for (int i = 0; i < 8; i++) {        // B2 [128k(h)][128n(d)] from w2
            int u = tid + 256 * i;
            int r = u >> 4, c8 = (u & 15) * 8;
            size_t s = (size_t)r * DM + v0 + c8;
            uint32_t o = (uint32_t)(r * HST + c8) * 2;
            *(uint4*)(sm + OFF_B2HI + o) = *(const uint4*)(w2h + s);
            *(uint4*)(sm + OFF_B2LO + o) = *(const uint4*)(w2l + s);
        }
        __syncthreads();

        float c2[2][4][4];
#pragma unroll
        for (int mi = 0; mi < 2; mi++)
#pragma unroll
            for (int ni = 0; ni < 4; ni++)
#pragma unroll
                for (int j = 0; j < 4; j++) c2[mi][ni][j] = 0.f;

#pragma unroll
        for (int ks = 0; ks < 8; ks++) {
            uint32_t ah[2][4], al[2][4];
#pragma unroll
            for (int mi = 0; mi < 2; mi++) {
                ldm_x4(ah[mi], a_addr(smb + OFF_HHI, HST, wm * 32 + mi * 16, ks * 16, lane));
                ldm_x4(al[mi], a_addr(smb + OFF_HLO, HST, wm * 32 + mi * 16, ks * 16, lane));
            }
            uint32_t bh[2][4], bl[2][4];
#pragma unroll
            for (int ng = 0; ng < 2; ng++) {
                ldm_x4t(bh[ng], bt_addr(smb + OFF_B2HI, HST, wn * 32 + ng * 16, ks * 16, lane));
                ldm_x4t(bl[ng], bt_addr(smb + OFF_B2LO, HST, wn * 32 + ng * 16, ks * 16, lane));
            }
#pragma unroll
            for (int mi = 0; mi < 2; mi++)
#pragma unroll
                for (int ni = 0; ni < 4; ni++) {
                    int ngp = ni >> 1, pr = (ni & 1) * 2;
                    mma_bf16(c2[mi][ni], ah[mi], bh[ngp][pr], bh[ngp][pr + 1]);
                    mma_bf16(c2[mi][ni], ah[mi], bl[ngp][pr], bl[ngp][pr + 1]);
                    mma_bf16(c2[mi][ni], al[mi], bh[ngp][pr], bh[ngp][pr + 1]);
                }
        }

        // store partials (deterministic, indexed by nk)
#pragma unroll
        for (int mi = 0; mi < 2; mi++) {
            int rA = wm * 32 + mi * 16 + g;
            int rB = rA + 8;
#pragma unroll
            for (int ni = 0; ni < 4; ni++) {
                int col = v0 + wn * 32 + ni * 8 + t4 * 2;
                if (rA < cnt) {
                    float2 o0; o0.x = c2[mi][ni][0]; o0.y = c2[mi][ni][1];
                    *(float2*)(g_buf + (size_t)nks[rA] * DM + col) = o0;
                }
                if (rB < cnt) {
                    float2 o1; o1.x = c2[mi][ni][2]; o1.y = c2[mi][ni][3];
                    *(float2*)(g_buf + (size_t)nks[rB] * DM + col) = o1;
                }
            }
        }
        __syncthreads();
    }
}

// ---------------- reduce 4 partials per token ----------------
__global__ void __launch_bounds__(256) k_reduce(float* __restrict__ y) {
    int t = blockIdx.x * 256 + threadIdx.x;
    int n  = t / (DM / 4);
    int v4 = t % (DM / 4);
    const float4* b = (const float4*)g_buf;
    float4 r0 = b[(size_t)(n * 4 + 0) * (DM / 4) + v4];
    float4 r1 = b[(size_t)(n * 4 + 1) * (DM / 4) + v4];
    float4 r2 = b[(size_t)(n * 4 + 2) * (DM / 4) + v4];
    float4 r3 = b[(size_t)(n * 4 + 3) * (DM / 4) + v4];
    float4 o;
    o.x = (r0.x + r1.x) + (r2.x + r3.x);
    o.y = (r0.y + r1.y) + (r2.y + r3.y);
    o.z = (r0.z + r1.z) + (r2.z + r3.z);
    o.w = (r0.w + r1.w) + (r2.w + r3.w);
    ((float4*)y)[t] = o;
}

extern "C" void kernel_launch(void* const* d_in, const int* in_sizes, int n_in,
                              void* d_out, int out_size) {
    const float* x   = (const float*)d_in[0];
    const float* sel = (const float*)d_in[1];
    const float* w1  = (const float*)d_in[2];
    const float* w2  = (const float*)d_in[3];
    float* y = (float*)d_out;

    cudaFuncSetAttribute(k_expert, cudaFuncAttributeMaxDynamicSharedMemorySize, SMEM_EXPERT);

    k_cvt<<<(XN + 2 * WN) / 4 / 256, 256>>>(x, w1, w2);
    k_score<<<NTOK / 128, 256>>>(x, sel);
    k_scan<<<1, 32>>>();
    k_fill<<<NK / 256, 256>>>();
    k_expert<<<dim3(NTOK / MT, EX), 256, SMEM_EXPERT>>>();
    k_reduce<<<NTOK * DM / 4 / 256, 256>>>(y);
}

// round 7
// speedup vs baseline: 1.7456x; 1.0310x over previous
#include <cuda_runtime.h>
#include <math.h>
#include <stdint.h>

#define NTOK 4096
#define DM   512
#define EX   32
#define HH   128
#define TOPK 4
#define NK   (NTOK*TOPK)
#define MT   64     // token tile
#define NBLK 32     // score/fill block count

// ---------------- device scratch (no allocs allowed) ----------------
__device__ int   g_bcnt[NBLK * EX];   // per-score-block expert counts (no zeroing needed)
__device__ int   g_route_e[NK];
__device__ float g_route_g[NK];
__device__ int   g_perm_nk[NK];
__device__ float g_perm_g[NK];
__device__ float g_buf[NK * DM];      // 32 MB partials indexed by (n*4+k)

// ---------------- helpers ----------------
__device__ __forceinline__ float to_tf32(float x) {
    float r;
    asm("cvt.rna.tf32.f32 %0, %1;" : "=f"(r) : "f"(x));
    return r;
}

__device__ __forceinline__ void mma_tf32(float* c, const uint32_t* a, uint32_t b0, uint32_t b1) {
    asm volatile(
        "mma.sync.aligned.m16n8k8.row.col.f32.tf32.tf32.f32 "
        "{%0,%1,%2,%3}, {%4,%5,%6,%7}, {%8,%9}, {%0,%1,%2,%3};"
        : "+f"(c[0]), "+f"(c[1]), "+f"(c[2]), "+f"(c[3])
        : "r"(a[0]), "r"(a[1]), "r"(a[2]), "r"(a[3]), "r"(b0), "r"(b1));
}

// exclusive offsets for expert `want` from g_bcnt; lane-parallel warp scan.
// Returns via pointers (called by threads with tid<32).
__device__ __forceinline__ void expert_offsets(int lane, int upto_block, int* tot_out,
                                               int* excl_out, int* pre_out) {
    int tot = 0, pre = 0;
#pragma unroll
    for (int b = 0; b < NBLK; b++) {
        int v = g_bcnt[b * EX + lane];
        tot += v;
        if (b < upto_block) pre += v;
    }
    int s = tot;
#pragma unroll
    for (int off = 1; off < 32; off <<= 1) {
        int v = __shfl_up_sync(0xffffffffu, s, off);
        if (lane >= off) s += v;
    }
    *tot_out = tot; *excl_out = s - tot; *pre_out = pre;
}

// ---------------- fused routing: scores (128 tok x 32 exp) + top-4 + counts ----------------
__global__ void __launch_bounds__(256) k_score(const float* __restrict__ x,
                                               const float* __restrict__ sel) {
    __shared__ float Xs[128][36];
    __shared__ float Bs[32][36];
    __shared__ float Ss[128][36];
    __shared__ int   scnt[EX];
    int tid = threadIdx.x;
    int n0 = blockIdx.x * 128;
    int trow = tid >> 3;
    int tc = (tid & 7) * 4;
    if (tid < EX) scnt[tid] = 0;
    float acc[4][4];
#pragma unroll
    for (int i = 0; i < 4; i++)
#pragma unroll
        for (int j = 0; j < 4; j++) acc[i][j] = 0.f;

    for (int k0 = 0; k0 < DM; k0 += 32) {
#pragma unroll
        for (int j = 0; j < 4; j++) {
            int u = tid + 256 * j;
            int r = u >> 3, c = (u & 7) * 4;
            *(float4*)&Xs[r][c] = *(const float4*)(x + (size_t)(n0 + r) * DM + k0 + c);
        }
        {
            int e = tid >> 3, kk = (tid & 7) * 4;
            float4 v = *(const float4*)(sel + (size_t)e * DM + k0 + kk);
            Bs[kk][e] = v.x; Bs[kk + 1][e] = v.y; Bs[kk + 2][e] = v.z; Bs[kk + 3][e] = v.w;
        }
        __syncthreads();
#pragma unroll
        for (int kk = 0; kk < 32; kk++) {
            float4 b = *(float4*)&Bs[kk][tc];
#pragma unroll
            for (int i = 0; i < 4; i++) {
                float a = Xs[trow + 32 * i][kk];
                acc[i][0] += a * b.x; acc[i][1] += a * b.y;
                acc[i][2] += a * b.z; acc[i][3] += a * b.w;
            }
        }
        __syncthreads();
    }
#pragma unroll
    for (int i = 0; i < 4; i++)
        *(float4*)&Ss[trow + 32 * i][tc] =
            make_float4(acc[i][0], acc[i][1], acc[i][2], acc[i][3]);
    __syncthreads();

    if (tid < 128) {
        int n = n0 + tid;
        float s[EX];
#pragma unroll
        for (int e = 0; e < EX; e++) s[e] = Ss[tid][e];
        for (int k = 0; k < TOPK; k++) {
            float best = -INFINITY; int bi = 0;
#pragma unroll
            for (int e = 0; e < EX; e++)
                if (s[e] > best) { best = s[e]; bi = e; }
            s[bi] = -INFINITY;
            g_route_e[n * TOPK + k] = bi;
            g_route_g[n * TOPK + k] = 1.f / (1.f + expf(-best));
            atomicAdd(&scnt[bi], 1);
        }
    }
    __syncthreads();
    if (tid < EX) g_bcnt[blockIdx.x * EX + tid] = scnt[tid];
}

// ---------------- fill: per-expert token lists (atomic-free across blocks) ----------------
__global__ void __launch_bounds__(512) k_fill() {
    __shared__ int sbase[EX], scnt[EX];
    int tid = threadIdx.x;
    if (tid < 32) {
        int tot, excl, pre;
        expert_offsets(tid, blockIdx.x, &tot, &excl, &pre);
        sbase[tid] = excl + pre;
        scnt[tid] = 0;
    }
    __syncthreads();
    int t = blockIdx.x * 512 + tid;
    int e = g_route_e[t];
    int lp = atomicAdd(&scnt[e], 1);
    int p = sbase[e] + lp;
    g_perm_nk[p] = t;
    g_perm_g[p] = g_route_g[t];
}

// ---------------- expert MLP: tf32 mma.sync, MT=64 ----------------
// strides (fp32 words): A-pattern needs S%32==4, B-pattern S%32==8
#define AS 68     // A tile [64m][64k]
#define BS 136    // B tiles [64k][128n]
#define HS 132    // H tile [64m][128k]
#define OFF_A1 0                        // 64*68*4  = 17408
#define OFF_B1 17408                    // 64*136*4 = 34816 (reused for B2 chunks)
#define OFF_H  52224                    // 64*132*4 = 33792
#define OFF_NK   86016
#define OFF_NROW 86272
#define OFF_GATE 86528
#define SMEM_EXPERT 86784

__global__ void __launch_bounds__(256, 2) k_expert(const float* __restrict__ x,
                                                   const float* __restrict__ w1,
                                                   const float* __restrict__ w2) {
    extern __shared__ char sm[];
    __shared__ int s_off, s_end;
    int tid = threadIdx.x, lane = tid & 31, wid = tid >> 5;
    int e = blockIdx.y;

    if (tid < 32) {
        int tot, excl, pre;
        expert_offsets(tid, 0, &tot, &excl, &pre);
        if (tid == e) { s_off = excl; s_end = excl + tot; }
    }
    __syncthreads();
    int base = s_off + blockIdx.x * MT;
    int end  = s_end;
    if (base >= end) return;
    int cnt = min(MT, end - base);

    int wm = wid & 1, wn = wid >> 1;     // 2x4 warp grid, 32x32 warp tiles
    float* As = (float*)(sm + OFF_A1);
    float* Bsh = (float*)(sm + OFF_B1);
    float* Hsm = (float*)(sm + OFF_H);
    int*   nks   = (int*)(sm + OFF_NK);
    int*   nrow  = (int*)(sm + OFF_NROW);
    float* gates = (float*)(sm + OFF_GATE);
    if (tid < MT) {
        if (tid < cnt) {
            int nk = g_perm_nk[base + tid];
            nks[tid] = nk; nrow[tid] = nk >> 2; gates[tid] = g_perm_g[base + tid];
        } else {
            nks[tid] = 0; nrow[tid] = 0; gates[tid] = 0.f;
        }
    }
    __syncthreads();

    const float* w1e = w1 + (size_t)e * DM * HH;   // [D,H]
    const float* w2e = w2 + (size_t)e * HH * DM;   // [H,D]

    int g = lane >> 2, t4 = lane & 3;
    int mrow0 = wm * 32, ncol0 = wn * 32;

    // ---- GEMM1: H[64,128] = X[64,512] * W1[512,128], K chunks of 64 ----
    float c1[2][4][4];
#pragma unroll
    for (int mi = 0; mi < 2; mi++)
#pragma unroll
        for (int ni = 0; ni < 4; ni++)
#pragma unroll
            for (int j = 0; j < 4; j++) c1[mi][ni][j] = 0.f;

    for (int kc = 0; kc < 8; kc++) {
        int k0 = kc * 64;
#pragma unroll
        for (int i = 0; i < 4; i++) {            // A: [64][64] gathered rows
            int u = tid + 256 * i;
            int r = u >> 4, c4 = (u & 15) * 4;
            float4 v = *(const float4*)(x + (size_t)nrow[r] * DM + k0 + c4);
            v.x = to_tf32(v.x); v.y = to_tf32(v.y); v.z = to_tf32(v.z); v.w = to_tf32(v.w);
            *(float4*)&As[r * AS + c4] = v;
        }
#pragma unroll
        for (int i = 0; i < 8; i++) {            // B1: [64k][128n] rows d=k0+r
            int u = tid + 256 * i;
            int r = u >> 5, c4 = (u & 31) * 4;
            float4 v = *(const float4*)(w1e + (size_t)(k0 + r) * HH + c4);
            v.x = to_tf32(v.x); v.y = to_tf32(v.y); v.z = to_tf32(v.z); v.w = to_tf32(v.w);
            *(float4*)&Bsh[r * BS + c4] = v;
        }
        __syncthreads();
#pragma unroll
        for (int ks = 0; ks < 8; ks++) {
            int kk = ks * 8;
            uint32_t a[2][4];
#pragma unroll
            for (int mi = 0; mi < 2; mi++) {
                int m = mrow0 + mi * 16;
                a[mi][0] = __float_as_uint(As[(m + g) * AS + kk + t4]);
                a[mi][1] = __float_as_uint(As[(m + g + 8) * AS + kk + t4]);
                a[mi][2] = __float_as_uint(As[(m + g) * AS + kk + t4 + 4]);
                a[mi][3] = __float_as_uint(As[(m + g + 8) * AS + kk + t4 + 4]);
            }
#pragma unroll
            for (int ni = 0; ni < 4; ni++) {
                int n = ncol0 + ni * 8;
                uint32_t b0 = __float_as_uint(Bsh[(kk + t4) * BS + n + g]);
                uint32_t b1 = __float_as_uint(Bsh[(kk + t4 + 4) * BS + n + g]);
#pragma unroll
                for (int mi = 0; mi < 2; mi++)
                    mma_tf32(c1[mi][ni], a[mi], b0, b1);
            }
        }
        __syncthreads();
    }

    // ---- H = tf32(relu(.)*gate) -> SMEM [64m][128k] ----
#pragma unroll
    for (int mi = 0; mi < 2; mi++) {
        int rA = mrow0 + mi * 16 + g;
        float gA = gates[rA], gB = gates[rA + 8];
#pragma unroll
        for (int ni = 0; ni < 4; ni++) {
            int col = ncol0 + ni * 8 + t4 * 2;
            float2 hA, hB;
            hA.x = to_tf32(fmaxf(c1[mi][ni][0], 0.f) * gA);
            hA.y = to_tf32(fmaxf(c1[mi][ni][1], 0.f) * gA);
            hB.x = to_tf32(fmaxf(c1[mi][ni][2], 0.f) * gB);
            hB.y = to_tf32(fmaxf(c1[mi][ni][3], 0.f) * gB);
            *(float2*)&Hsm[rA * HS + col] = hA;
            *(float2*)&Hsm[(rA + 8) * HS + col] = hB;
        }
    }
    __syncthreads();

    // ---- GEMM2: Y[64,512] = H[64,128] * W2[128,512], per 128-col v chunk ----
    for (int v = 0; v < 4; v++) {
        int v0 = v * 128;
        float c2[2][4][4];
#pragma unroll
        for (int mi = 0; mi < 2; mi++)
#pragma unroll
            for (int ni = 0; ni < 4; ni++)
#pragma unroll
                for (int j = 0; j < 4; j++) c2[mi][ni][j] = 0.f;

        for (int kc2 = 0; kc2 < 2; kc2++) {
#pragma unroll
            for (int i = 0; i < 8; i++) {        // B2: [64k(h)][128n(d)]
                int u = tid + 256 * i;
                int r = u >> 5, c4 = (u & 31) * 4;
                float4 w = *(const float4*)(w2e + (size_t)(kc2 * 64 + r) * DM + v0 + c4);
                w.x = to_tf32(w.x); w.y = to_tf32(w.y); w.z = to_tf32(w.z); w.w = to_tf32(w.w);
                *(float4*)&Bsh[r * BS + c4] = w;
            }
            __syncthreads();
#pragma unroll
            for (int ks = 0; ks < 8; ks++) {
                int kh = kc2 * 64 + ks * 8;      // k index into H
                int kk = ks * 8;                 // k index into staged B
                uint32_t a[2][4];
#pragma unroll
                for (int mi = 0; mi < 2; mi++) {
                    int m = mrow0 + mi * 16;
                    a[mi][0] = __float_as_uint(Hsm[(m + g) * HS + kh + t4]);
                    a[mi][1] = __float_as_uint(Hsm[(m + g + 8) * HS + kh + t4]);
                    a[mi][2] = __float_as_uint(Hsm[(m + g) * HS + kh + t4 + 4]);
                    a[mi][3] = __float_as_uint(Hsm[(m + g + 8) * HS + kh + t4 + 4]);
                }
#pragma unroll
                for (int ni = 0; ni < 4; ni++) {
                    int n = ncol0 + ni * 8;
                    uint32_t b0 = __float_as_uint(Bsh[(kk + t4) * BS + n + g]);
                    uint32_t b1 = __float_as_uint(Bsh[(kk + t4 + 4) * BS + n + g]);
#pragma unroll
                    for (int mi = 0; mi < 2; mi++)
                        mma_tf32(c2[mi][ni], a[mi], b0, b1);
                }
            }
            __syncthreads();
        }

        // store partials (deterministic, indexed by nk)
#pragma unroll
        for (int mi = 0; mi < 2; mi++) {
            int rA = mrow0 + mi * 16 + g;
            int rB = rA + 8;
#pragma unroll
            for (int ni = 0; ni < 4; ni++) {
                int col = v0 + ncol0 + ni * 8 + t4 * 2;
                if (rA < cnt) {
                    float2 o0; o0.x = c2[mi][ni][0]; o0.y = c2[mi][ni][1];
                    *(float2*)(g_buf + (size_t)nks[rA] * DM + col) = o0;
                }
                if (rB < cnt) {
                    float2 o1; o1.x = c2[mi][ni][2]; o1.y = c2[mi][ni][3];
                    *(float2*)(g_buf + (size_t)nks[rB] * DM + col) = o1;
                }
            }
        }
    }
}

// ---------------- reduce 4 partials per token ----------------
__global__ void __launch_bounds__(256) k_reduce(float* __restrict__ y) {
    int t = blockIdx.x * 256 + threadIdx.x;
    int n  = t / (DM / 4);
    int v4 = t % (DM / 4);
    const float4* b = (const float4*)g_buf;
    float4 r0 = b[(size_t)(n * 4 + 0) * (DM / 4) + v4];
    float4 r1 = b[(size_t)(n * 4 + 1) * (DM / 4) + v4];
    float4 r2 = b[(size_t)(n * 4 + 2) * (DM / 4) + v4];
    float4 r3 = b[(size_t)(n * 4 + 3) * (DM / 4) + v4];
    float4 o;
    o.x = (r0.x + r1.x) + (r2.x + r3.x);
    o.y = (r0.y + r1.y) + (r2.y + r3.y);
    o.z = (r0.z + r1.z) + (r2.z + r3.z);
    o.w = (r0.w + r1.w) + (r2.w + r3.w);
    ((float4*)y)[t] = o;
}

extern "C" void kernel_launch(void* const* d_in, const int* in_sizes, int n_in,
                              void* d_out, int out_size) {
    const float* x   = (const float*)d_in[0];
    const float* sel = (const float*)d_in[1];
    const float* w1  = (const float*)d_in[2];
    const float* w2  = (const float*)d_in[3];
    float* y = (float*)d_out;

    cudaFuncSetAttribute(k_expert, cudaFuncAttributeMaxDynamicSharedMemorySize, SMEM_EXPERT);

    k_score<<<NBLK, 256>>>(x, sel);
    k_fill<<<NBLK, 512>>>();
    k_expert<<<dim3(NTOK / MT, EX), 256, SMEM_EXPERT>>>(x, w1, w2);
    k_reduce<<<NTOK * DM / 4 / 256, 256>>>(y);
}

// round 8
// speedup vs baseline: 1.8238x; 1.0448x over previous
#include <cuda_runtime.h>
#include <math.h>
#include <stdint.h>

#define NTOK 4096
#define DM   512
#define EX   32
#define HH   128
#define TOPK 4
#define NK   (NTOK*TOPK)
#define MT   64     // expert token tile
#define NBLK 128    // score/fill block count

// ---------------- device scratch (no allocs allowed) ----------------
__device__ int   g_bcnt[NBLK * EX];   // per-score-block expert counts (rewritten each launch)
__device__ int   g_route_e[NK];
__device__ float g_route_g[NK];
__device__ int   g_perm_nk[NK];
__device__ float g_perm_g[NK];
__device__ float g_buf[NK * DM];      // 32 MB partials indexed by (n*4+k)

// ---------------- helpers ----------------
__device__ __forceinline__ float to_tf32(float x) {
    float r;
    asm("cvt.rna.tf32.f32 %0, %1;" : "=f"(r) : "f"(x));
    return r;
}

__device__ __forceinline__ void mma_tf32(float* c, const uint32_t* a, uint32_t b0, uint32_t b1) {
    asm volatile(
        "mma.sync.aligned.m16n8k8.row.col.f32.tf32.tf32.f32 "
        "{%0,%1,%2,%3}, {%4,%5,%6,%7}, {%8,%9}, {%0,%1,%2,%3};"
        : "+f"(c[0]), "+f"(c[1]), "+f"(c[2]), "+f"(c[3])
        : "r"(a[0]), "r"(a[1]), "r"(a[2]), "r"(a[3]), "r"(b0), "r"(b1));
}

// expert offsets from g_bcnt; lane-parallel warp scan (call with tid<32).
__device__ __forceinline__ void expert_offsets(int lane, int upto_block, int* tot_out,
                                               int* excl_out, int* pre_out) {
    int tot = 0, pre = 0;
    for (int b = 0; b < NBLK; b++) {
        int v = g_bcnt[b * EX + lane];
        tot += v;
        if (b < upto_block) pre += v;
    }
    int s = tot;
#pragma unroll
    for (int off = 1; off < 32; off <<= 1) {
        int v = __shfl_up_sync(0xffffffffu, s, off);
        if (lane >= off) s += v;
    }
    *tot_out = tot; *excl_out = s - tot; *pre_out = pre;
}

// ---------------- fused routing: 32 tokens x 32 experts per block ----------------
__global__ void __launch_bounds__(256) k_score(const float* __restrict__ x,
                                               const float* __restrict__ sel) {
    __shared__ float Xs[32][36];
    __shared__ float Bs[32][36];
    __shared__ float Ss[32][36];
    __shared__ int   scnt[EX];
    int tid = threadIdx.x;
    int n0 = blockIdx.x * 32;
    int trow = tid >> 3;
    int tc = (tid & 7) * 4;
    if (tid < EX) scnt[tid] = 0;
    float acc[4] = {0.f, 0.f, 0.f, 0.f};

    for (int k0 = 0; k0 < DM; k0 += 32) {
        {
            int r = tid >> 3, c = (tid & 7) * 4;
            *(float4*)&Xs[r][c] = *(const float4*)(x + (size_t)(n0 + r) * DM + k0 + c);
        }
        {
            int e = tid >> 3, kk = (tid & 7) * 4;
            float4 v = *(const float4*)(sel + (size_t)e * DM + k0 + kk);
            Bs[kk][e] = v.x; Bs[kk + 1][e] = v.y; Bs[kk + 2][e] = v.z; Bs[kk + 3][e] = v.w;
        }
        __syncthreads();
#pragma unroll
        for (int kk = 0; kk < 32; kk++) {
            float a = Xs[trow][kk];
            float4 b = *(float4*)&Bs[kk][tc];
            acc[0] += a * b.x; acc[1] += a * b.y; acc[2] += a * b.z; acc[3] += a * b.w;
        }
        __syncthreads();
    }
    *(float4*)&Ss[trow][tc] = make_float4(acc[0], acc[1], acc[2], acc[3]);
    __syncthreads();

    if (tid < 32) {
        int n = n0 + tid;
        float s[EX];
#pragma unroll
        for (int e = 0; e < EX; e++) s[e] = Ss[tid][e];
        for (int k = 0; k < TOPK; k++) {
            float best = -INFINITY; int bi = 0;
#pragma unroll
            for (int e = 0; e < EX; e++)
                if (s[e] > best) { best = s[e]; bi = e; }
            s[bi] = -INFINITY;
            g_route_e[n * TOPK + k] = bi;
            g_route_g[n * TOPK + k] = 1.f / (1.f + expf(-best));
            atomicAdd(&scnt[bi], 1);
        }
    }
    __syncthreads();
    if (tid < EX) g_bcnt[blockIdx.x * EX + tid] = scnt[tid];
}

// ---------------- fill: per-expert token lists ----------------
__global__ void __launch_bounds__(128) k_fill() {
    __shared__ int sbase[EX], scnt[EX];
    int tid = threadIdx.x;
    if (tid < 32) {
        int tot, excl, pre;
        expert_offsets(tid, blockIdx.x, &tot, &excl, &pre);
        sbase[tid] = excl + pre;
        scnt[tid] = 0;
    }
    __syncthreads();
    int t = blockIdx.x * 128 + tid;
    int e = g_route_e[t];
    int lp = atomicAdd(&scnt[e], 1);
    int p = sbase[e] + lp;
    g_perm_nk[p] = t;
    g_perm_g[p] = g_route_g[t];
}

// ---------------- expert MLP: tf32 mma.sync, pipelined 32-K chunks ----------------
#define AS 36     // A tile stride [64m][32k]
#define BS 136    // B tile stride [32k][128n]
#define HS 132    // H tile stride [64m][128k]
#define OFF_A 0                         // 2*64*36*4  = 18432
#define OFF_B 18432                     // 2*32*136*4 = 34816
#define OFF_H 53248                     // 64*132*4   = 33792
#define OFF_NK   87040
#define OFF_NROW 87296
#define OFF_GATE 87552
#define SMEM_EXPERT 87808

__global__ void __launch_bounds__(256, 2) k_expert(const float* __restrict__ x,
                                                   const float* __restrict__ w1,
                                                   const float* __restrict__ w2) {
    extern __shared__ char sm[];
    __shared__ int s_off, s_end;
    int tid = threadIdx.x, lane = tid & 31, wid = tid >> 5;
    int e = blockIdx.y;

    if (tid < 32) {
        int tot, excl, pre;
        expert_offsets(tid, 0, &tot, &excl, &pre);
        if (tid == e) { s_off = excl; s_end = excl + tot; }
    }
    __syncthreads();
    int base = s_off + blockIdx.x * MT;
    int end  = s_end;
    if (base >= end) return;
    int cnt = min(MT, end - base);

    int wm = wid & 1, wn = wid >> 1;     // 2x4 warp grid, 32x32 warp tiles
    float* As0 = (float*)(sm + OFF_A);           // [2][64][36]
    float* Bs0 = (float*)(sm + OFF_B);           // [2][32][136]
    float* Hsm = (float*)(sm + OFF_H);           // [64][132]
    int*   nks   = (int*)(sm + OFF_NK);
    int*   nrow  = (int*)(sm + OFF_NROW);
    float* gates = (float*)(sm + OFF_GATE);
    if (tid < MT) {
        if (tid < cnt) {
            int nk = g_perm_nk[base + tid];
            nks[tid] = nk; nrow[tid] = nk >> 2; gates[tid] = g_perm_g[base + tid];
        } else {
            nks[tid] = 0; nrow[tid] = 0; gates[tid] = 0.f;
        }
    }
    __syncthreads();

    const float* w1e = w1 + (size_t)e * DM * HH;   // [D,H]
    const float* w2e = w2 + (size_t)e * HH * DM;   // [H,D]

    int g = lane >> 2, t4 = lane & 3;
    int mrow0 = wm * 32, ncol0 = wn * 32;

    // staging thread coords (fixed per thread)
    int ar0 = tid >> 3,        ac0 = (tid & 7) * 4;    // A: row, col (i=0); i=1 -> row+32
    int br0 = tid >> 5,        bc0 = (tid & 31) * 4;   // B: row (i adds 8), col

    float4 ra[2], rb[4];

    // ---- GEMM1: H[64,128] = X[64,512] * W1[512,128], 16 chunks of K=32 ----
    float c1[2][4][4];
#pragma unroll
    for (int mi = 0; mi < 2; mi++)
#pragma unroll
        for (int ni = 0; ni < 4; ni++)
#pragma unroll
            for (int j = 0; j < 4; j++) c1[mi][ni][j] = 0.f;

    // prefetch chunk 0
#pragma unroll
    for (int i = 0; i < 2; i++)
        ra[i] = *(const float4*)(x + (size_t)nrow[ar0 + 32 * i] * DM + ac0);
#pragma unroll
    for (int i = 0; i < 4; i++)
        rb[i] = *(const float4*)(w1e + (size_t)(br0 + 8 * i) * HH + bc0);
    {
        float* As = As0;
        float* Bsh = Bs0;
#pragma unroll
        for (int i = 0; i < 2; i++) {
            float4 v = ra[i];
            v.x = to_tf32(v.x); v.y = to_tf32(v.y); v.z = to_tf32(v.z); v.w = to_tf32(v.w);
            *(float4*)&As[(ar0 + 32 * i) * AS + ac0] = v;
        }
#pragma unroll
        for (int i = 0; i < 4; i++) {
            float4 v = rb[i];
            v.x = to_tf32(v.x); v.y = to_tf32(v.y); v.z = to_tf32(v.z); v.w = to_tf32(v.w);
            *(float4*)&Bsh[(br0 + 8 * i) * BS + bc0] = v;
        }
    }
    __syncthreads();

    int p = 0;
    for (int kc = 0; kc < 16; kc++) {
        if (kc < 15) {
            int k0 = (kc + 1) * 32;
#pragma unroll
            for (int i = 0; i < 2; i++)
                ra[i] = *(const float4*)(x + (size_t)nrow[ar0 + 32 * i] * DM + k0 + ac0);
#pragma unroll
            for (int i = 0; i < 4; i++)
                rb[i] = *(const float4*)(w1e + (size_t)(k0 + br0 + 8 * i) * HH + bc0);
        }
        float* As = As0 + p * 64 * AS;
        float* Bsh = Bs0 + p * 32 * BS;
#pragma unroll
        for (int ks = 0; ks < 4; ks++) {
            int kk = ks * 8;
            uint32_t a[2][4];
#pragma unroll
            for (int mi = 0; mi < 2; mi++) {
                int m = mrow0 + mi * 16;
                a[mi][0] = __float_as_uint(As[(m + g) * AS + kk + t4]);
                a[mi][1] = __float_as_uint(As[(m + g + 8) * AS + kk + t4]);
                a[mi][2] = __float_as_uint(As[(m + g) * AS + kk + t4 + 4]);
                a[mi][3] = __float_as_uint(As[(m + g + 8) * AS + kk + t4 + 4]);
            }
#pragma unroll
            for (int ni = 0; ni < 4; ni++) {
                int n = ncol0 + ni * 8;
                uint32_t b0 = __float_as_uint(Bsh[(kk + t4) * BS + n + g]);
                uint32_t b1 = __float_as_uint(Bsh[(kk + t4 + 4) * BS + n + g]);
#pragma unroll
                for (int mi = 0; mi < 2; mi++)
                    mma_tf32(c1[mi][ni], a[mi], b0, b1);
            }
        }
        if (kc < 15) {
            float* Asn = As0 + (1 - p) * 64 * AS;
            float* Bsn = Bs0 + (1 - p) * 32 * BS;
#pragma unroll
            for (int i = 0; i < 2; i++) {
                float4 v = ra[i];
                v.x = to_tf32(v.x); v.y = to_tf32(v.y); v.z = to_tf32(v.z); v.w = to_tf32(v.w);
                *(float4*)&Asn[(ar0 + 32 * i) * AS + ac0] = v;
            }
#pragma unroll
            for (int i = 0; i < 4; i++) {
                float4 v = rb[i];
                v.x = to_tf32(v.x); v.y = to_tf32(v.y); v.z = to_tf32(v.z); v.w = to_tf32(v.w);
                *(float4*)&Bsn[(br0 + 8 * i) * BS + bc0] = v;
            }
        }
        __syncthreads();
        p ^= 1;
    }

    // ---- H = tf32(relu(.)*gate) -> SMEM [64m][128k] ----
#pragma unroll
    for (int mi = 0; mi < 2; mi++) {
        int rA = mrow0 + mi * 16 + g;
        float gA = gates[rA], gB = gates[rA + 8];
#pragma unroll
        for (int ni = 0; ni < 4; ni++) {
            int col = ncol0 + ni * 8 + t4 * 2;
            float2 hA, hB;
            hA.x = to_tf32(fmaxf(c1[mi][ni][0], 0.f) * gA);
            hA.y = to_tf32(fmaxf(c1[mi][ni][1], 0.f) * gA);
            hB.x = to_tf32(fmaxf(c1[mi][ni][2], 0.f) * gB);
            hB.y = to_tf32(fmaxf(c1[mi][ni][3], 0.f) * gB);
            *(float2*)&Hsm[rA * HS + col] = hA;
            *(float2*)&Hsm[(rA + 8) * HS + col] = hB;
        }
    }
    __syncthreads();

    // ---- GEMM2: Y[64,512] = H[64,128] * W2[128,512]; 16 chunks = (v, kch) ----
    float c2[2][4][4];
#pragma unroll
    for (int mi = 0; mi < 2; mi++)
#pragma unroll
        for (int ni = 0; ni < 4; ni++)
#pragma unroll
            for (int j = 0; j < 4; j++) c2[mi][ni][j] = 0.f;

    // prefetch chunk 0 (v=0, kch=0)
#pragma unroll
    for (int i = 0; i < 4; i++)
        rb[i] = *(const float4*)(w2e + (size_t)(br0 + 8 * i) * DM + bc0);
    {
        float* Bsh = Bs0;
#pragma unroll
        for (int i = 0; i < 4; i++) {
            float4 v = rb[i];
            v.x = to_tf32(v.x); v.y = to_tf32(v.y); v.z = to_tf32(v.z); v.w = to_tf32(v.w);
            *(float4*)&Bsh[(br0 + 8 * i) * BS + bc0] = v;
        }
    }
    __syncthreads();

    p = 0;
    for (int c = 0; c < 16; c++) {
        int v = c >> 2, kch = c & 3;
        if (c < 15) {
            int vn = (c + 1) >> 2, kn = (c + 1) & 3;
#pragma unroll
            for (int i = 0; i < 4; i++)
                rb[i] = *(const float4*)(w2e + (size_t)(kn * 32 + br0 + 8 * i) * DM +
                                         vn * 128 + bc0);
        }
        float* Bsh = Bs0 + p * 32 * BS;
#pragma unroll
        for (int ks = 0; ks < 4; ks++) {
            int kh = kch * 32 + ks * 8;          // k into H
            int kk = ks * 8;                     // k into staged B
            uint32_t a[2][4];
#pragma unroll
            for (int mi = 0; mi < 2; mi++) {
                int m = mrow0 + mi * 16;
                a[mi][0] = __float_as_uint(Hsm[(m + g) * HS + kh + t4]);
                a[mi][1] = __float_as_uint(Hsm[(m + g + 8) * HS + kh + t4]);
                a[mi][2] = __float_as_uint(Hsm[(m + g) * HS + kh + t4 + 4]);
                a[mi][3] = __float_as_uint(Hsm[(m + g + 8) * HS + kh + t4 + 4]);
            }
#pragma unroll
            for (int ni = 0; ni < 4; ni++) {
                int n = ncol0 + ni * 8;
                uint32_t b0 = __float_as_uint(Bsh[(kk + t4) * BS + n + g]);
                uint32_t b1 = __float_as_uint(Bsh[(kk + t4 + 4) * BS + n + g]);
#pragma unroll
                for (int mi = 0; mi < 2; mi++)
                    mma_tf32(c2[mi][ni], a[mi], b0, b1);
            }
        }
        if (c < 15) {
            float* Bsn = Bs0 + (1 - p) * 32 * BS;
#pragma unroll
            for (int i = 0; i < 4; i++) {
                float4 w = rb[i];
                w.x = to_tf32(w.x); w.y = to_tf32(w.y); w.z = to_tf32(w.z); w.w = to_tf32(w.w);
                *(float4*)&Bsn[(br0 + 8 * i) * BS + bc0] = w;
            }
        }
        __syncthreads();
        p ^= 1;

        if (kch == 3) {
            int v0 = v * 128;
#pragma unroll
            for (int mi = 0; mi < 2; mi++) {
                int rA = mrow0 + mi * 16 + g;
                int rB = rA + 8;
#pragma unroll
                for (int ni = 0; ni < 4; ni++) {
                    int col = v0 + ncol0 + ni * 8 + t4 * 2;
                    if (rA < cnt) {
                        float2 o0; o0.x = c2[mi][ni][0]; o0.y = c2[mi][ni][1];
                        *(float2*)(g_buf + (size_t)nks[rA] * DM + col) = o0;
                    }
                    if (rB < cnt) {
                        float2 o1; o1.x = c2[mi][ni][2]; o1.y = c2[mi][ni][3];
                        *(float2*)(g_buf + (size_t)nks[rB] * DM + col) = o1;
                    }
                    c2[mi][ni][0] = 0.f; c2[mi][ni][1] = 0.f;
                    c2[mi][ni][2] = 0.f; c2[mi][ni][3] = 0.f;
                }
            }
        }
    }
}

// ---------------- reduce 4 partials per token ----------------
__global__ void __launch_bounds__(256) k_reduce(float* __restrict__ y) {
    int t = blockIdx.x * 256 + threadIdx.x;
    int n  = t / (DM / 4);
    int v4 = t % (DM / 4);
    const float4* b = (const float4*)g_buf;
    float4 r0 = b[(size_t)(n * 4 + 0) * (DM / 4) + v4];
    float4 r1 = b[(size_t)(n * 4 + 1) * (DM / 4) + v4];
    float4 r2 = b[(size_t)(n * 4 + 2) * (DM / 4) + v4];
    float4 r3 = b[(size_t)(n * 4 + 3) * (DM / 4) + v4];
    float4 o;
    o.x = (r0.x + r1.x) + (r2.x + r3.x);
    o.y = (r0.y + r1.y) + (r2.y + r3.y);
    o.z = (r0.z + r1.z) + (r2.z + r3.z);
    o.w = (r0.w + r1.w) + (r2.w + r3.w);
    ((float4*)y)[t] = o;
}

extern "C" void kernel_launch(void* const* d_in, const int* in_sizes, int n_in,
                              void* d_out, int out_size) {
    const float* x   = (const float*)d_in[0];
    const float* sel = (const float*)d_in[1];
    const float* w1  = (const float*)d_in[2];
    const float* w2  = (const float*)d_in[3];
    float* y = (float*)d_out;

    cudaFuncSetAttribute(k_expert, cudaFuncAttributeMaxDynamicSharedMemorySize, SMEM_EXPERT);

    k_score<<<NBLK, 256>>>(x, sel);
    k_fill<<<NBLK, 128>>>();
    k_expert<<<dim3(NTOK / MT, EX), 256, SMEM_EXPERT>>>(x, w1, w2);
    k_reduce<<<NTOK * DM / 4 / 256, 256>>>(y);
}

// round 9
// speedup vs baseline: 1.9707x; 1.0806x over previous
#include <cuda_runtime.h>
#include <math.h>
#include <stdint.h>

#define NTOK 4096
#define DM   512
#define EX   32
#define HH   128
#define TOPK 4
#define NK   (NTOK*TOPK)
#define MT   64     // expert token tile
#define NBLK 128    // score/fill block count

// ---------------- device scratch (no allocs allowed) ----------------
__device__ int   g_bcnt[NBLK * EX];     // per-score-block expert counts
__device__ int   g_offsets[EX + 1];     // exclusive expert offsets
__device__ int   g_fillbase[NBLK * EX]; // per-fill-block write bases
__device__ int   g_tokcnt[NTOK];        // per-token completion counters
__device__ int   g_route_e[NK];
__device__ float g_route_g[NK];
__device__ int   g_perm_nk[NK];
__device__ float g_perm_g[NK];
__device__ float g_buf[NK * DM];        // 32 MB partials indexed by (n*4+k)

// ---------------- helpers ----------------
__device__ __forceinline__ float to_tf32(float x) {
    float r;
    asm("cvt.rna.tf32.f32 %0, %1;" : "=f"(r) : "f"(x));
    return r;
}

__device__ __forceinline__ void mma_tf32(float* c, const uint32_t* a, uint32_t b0, uint32_t b1) {
    asm volatile(
        "mma.sync.aligned.m16n8k8.row.col.f32.tf32.tf32.f32 "
        "{%0,%1,%2,%3}, {%4,%5,%6,%7}, {%8,%9}, {%0,%1,%2,%3};"
        : "+f"(c[0]), "+f"(c[1]), "+f"(c[2]), "+f"(c[3])
        : "r"(a[0]), "r"(a[1]), "r"(a[2]), "r"(a[3]), "r"(b0), "r"(b1));
}

// ---------------- fused routing: 32 tokens x 32 experts per block ----------------
__global__ void __launch_bounds__(256) k_score(const float* __restrict__ x,
                                               const float* __restrict__ sel) {
    __shared__ float Xs[32][36];
    __shared__ float Bs[32][36];
    __shared__ float Ss[32][36];
    __shared__ int   scnt[EX];
    int tid = threadIdx.x;
    int n0 = blockIdx.x * 32;
    int trow = tid >> 3;
    int tc = (tid & 7) * 4;
    if (tid < EX) scnt[tid] = 0;
    if (tid < 32) g_tokcnt[n0 + tid] = 0;     // zero completion counters
    float acc[4] = {0.f, 0.f, 0.f, 0.f};

    for (int k0 = 0; k0 < DM; k0 += 32) {
        {
            int r = tid >> 3, c = (tid & 7) * 4;
            *(float4*)&Xs[r][c] = *(const float4*)(x + (size_t)(n0 + r) * DM + k0 + c);
        }
        {
            int e = tid >> 3, kk = (tid & 7) * 4;
            float4 v = *(const float4*)(sel + (size_t)e * DM + k0 + kk);
            Bs[kk][e] = v.x; Bs[kk + 1][e] = v.y; Bs[kk + 2][e] = v.z; Bs[kk + 3][e] = v.w;
        }
        __syncthreads();
#pragma unroll
        for (int kk = 0; kk < 32; kk++) {
            float a = Xs[trow][kk];
            float4 b = *(float4*)&Bs[kk][tc];
            acc[0] += a * b.x; acc[1] += a * b.y; acc[2] += a * b.z; acc[3] += a * b.w;
        }
        __syncthreads();
    }
    *(float4*)&Ss[trow][tc] = make_float4(acc[0], acc[1], acc[2], acc[3]);
    __syncthreads();

    if (tid < 32) {
        int n = n0 + tid;
        float s[EX];
#pragma unroll
        for (int e = 0; e < EX; e++) s[e] = Ss[tid][e];
        for (int k = 0; k < TOPK; k++) {
            float best = -INFINITY; int bi = 0;
#pragma unroll
            for (int e = 0; e < EX; e++)
                if (s[e] > best) { best = s[e]; bi = e; }
            s[bi] = -INFINITY;
            g_route_e[n * TOPK + k] = bi;
            g_route_g[n * TOPK + k] = 1.f / (1.f + expf(-best));
            atomicAdd(&scnt[bi], 1);
        }
    }
    __syncthreads();
    if (tid < EX) g_bcnt[blockIdx.x * EX + tid] = scnt[tid];
}

// ---------------- scan: offsets + per-fill-block bases (1 warp) ----------------
__global__ void k_scan() {
    int lane = threadIdx.x;
    int tot = 0;
    for (int b = 0; b < NBLK; b++) tot += g_bcnt[b * EX + lane];
    int s = tot;
#pragma unroll
    for (int off = 1; off < 32; off <<= 1) {
        int v = __shfl_up_sync(0xffffffffu, s, off);
        if (lane >= off) s += v;
    }
    int excl = s - tot;
    g_offsets[lane] = excl;
    if (lane == EX - 1) g_offsets[EX] = s;
    int run = excl;
    for (int b = 0; b < NBLK; b++) {
        g_fillbase[b * EX + lane] = run;
        run += g_bcnt[b * EX + lane];
    }
}

// ---------------- fill: per-expert token lists ----------------
__global__ void __launch_bounds__(128) k_fill() {
    __shared__ int sbase[EX], scnt[EX];
    int tid = threadIdx.x;
    if (tid < 32) {
        sbase[tid] = g_fillbase[blockIdx.x * EX + tid];
        scnt[tid] = 0;
    }
    __syncthreads();
    int t = blockIdx.x * 128 + tid;
    int e = g_route_e[t];
    int lp = atomicAdd(&scnt[e], 1);
    int p = sbase[e] + lp;
    g_perm_nk[p] = t;
    g_perm_g[p] = g_route_g[t];
}

// ---------------- expert MLP: tf32 mma.sync, pipelined, fused output reduce ----------------
#define AS 36     // A tile stride [64m][32k]
#define BS 136    // B tile stride [32k][128n]
#define HS 132    // H tile stride [64m][128k]
#define OFF_A 0                         // 2*64*36*4  = 18432
#define OFF_B 18432                     // 2*32*136*4 = 34816
#define OFF_H 53248                     // 64*132*4   = 33792
#define OFF_NK   87040
#define OFF_NROW 87296
#define OFF_GATE 87552
#define SMEM_EXPERT 87808

__global__ void __launch_bounds__(256, 2) k_expert(const float* __restrict__ x,
                                                   const float* __restrict__ w1,
                                                   const float* __restrict__ w2,
                                                   float* __restrict__ y) {
    extern __shared__ char sm[];
    __shared__ int winners[MT];
    __shared__ int nwin;
    int tid = threadIdx.x, lane = tid & 31, wid = tid >> 5;
    int e = blockIdx.y;

    int off0 = g_offsets[e], off1 = g_offsets[e + 1];
    int base = off0 + blockIdx.x * MT;
    if (base >= off1) return;
    int cnt = min(MT, off1 - base);

    int wm = wid & 1, wn = wid >> 1;     // 2x4 warp grid, 32x32 warp tiles
    float* As0 = (float*)(sm + OFF_A);           // [2][64][36]
    float* Bs0 = (float*)(sm + OFF_B);           // [2][32][136]
    float* Hsm = (float*)(sm + OFF_H);           // [64][132]
    int*   nks   = (int*)(sm + OFF_NK);
    int*   nrow  = (int*)(sm + OFF_NROW);
    float* gates = (float*)(sm + OFF_GATE);
    if (tid == 0) nwin = 0;
    if (tid < MT) {
        if (tid < cnt) {
            int nk = g_perm_nk[base + tid];
            nks[tid] = nk; nrow[tid] = nk >> 2; gates[tid] = g_perm_g[base + tid];
        } else {
            nks[tid] = 0; nrow[tid] = 0; gates[tid] = 0.f;
        }
    }
    __syncthreads();

    const float* w1e = w1 + (size_t)e * DM * HH;   // [D,H]
    const float* w2e = w2 + (size_t)e * HH * DM;   // [H,D]

    int g = lane >> 2, t4 = lane & 3;
    int mrow0 = wm * 32, ncol0 = wn * 32;

    // staging thread coords (fixed per thread)
    int ar0 = tid >> 3,        ac0 = (tid & 7) * 4;    // A: row, col (i=0); i=1 -> row+32
    int br0 = tid >> 5,        bc0 = (tid & 31) * 4;   // B: row (i adds 8), col

    float4 ra[2], rb[4];

    // ---- GEMM1: H[64,128] = X[64,512] * W1[512,128], 16 chunks of K=32 ----
    float c1[2][4][4];
#pragma unroll
    for (int mi = 0; mi < 2; mi++)
#pragma unroll
        for (int ni = 0; ni < 4; ni++)
#pragma unroll
            for (int j = 0; j < 4; j++) c1[mi][ni][j] = 0.f;

    // prefetch chunk 0
#pragma unroll
    for (int i = 0; i < 2; i++)
        ra[i] = *(const float4*)(x + (size_t)nrow[ar0 + 32 * i] * DM + ac0);
#pragma unroll
    for (int i = 0; i < 4; i++)
        rb[i] = *(const float4*)(w1e + (size_t)(br0 + 8 * i) * HH + bc0);
    {
        float* As = As0;
        float* Bsh = Bs0;
#pragma unroll
        for (int i = 0; i < 2; i++) {
            float4 v = ra[i];
            v.x = to_tf32(v.x); v.y = to_tf32(v.y); v.z = to_tf32(v.z); v.w = to_tf32(v.w);
            *(float4*)&As[(ar0 + 32 * i) * AS + ac0] = v;
        }
#pragma unroll
        for (int i = 0; i < 4; i++) {
            float4 v = rb[i];
            v.x = to_tf32(v.x); v.y = to_tf32(v.y); v.z = to_tf32(v.z); v.w = to_tf32(v.w);
            *(float4*)&Bsh[(br0 + 8 * i) * BS + bc0] = v;
        }
    }
    __syncthreads();

    int p = 0;
    for (int kc = 0; kc < 16; kc++) {
        if (kc < 15) {
            int k0 = (kc + 1) * 32;
#pragma unroll
            for (int i = 0; i < 2; i++)
                ra[i] = *(const float4*)(x + (size_t)nrow[ar0 + 32 * i] * DM + k0 + ac0);
#pragma unroll
            for (int i = 0; i < 4; i++)
                rb[i] = *(const float4*)(w1e + (size_t)(k0 + br0 + 8 * i) * HH + bc0);
        }
        float* As = As0 + p * 64 * AS;
        float* Bsh = Bs0 + p * 32 * BS;
#pragma unroll
        for (int ks = 0; ks < 4; ks++) {
            int kk = ks * 8;
            uint32_t a[2][4];
#pragma unroll
            for (int mi = 0; mi < 2; mi++) {
                int m = mrow0 + mi * 16;
                a[mi][0] = __float_as_uint(As[(m + g) * AS + kk + t4]);
                a[mi][1] = __float_as_uint(As[(m + g + 8) * AS + kk + t4]);
                a[mi][2] = __float_as_uint(As[(m + g) * AS + kk + t4 + 4]);
                a[mi][3] = __float_as_uint(As[(m + g + 8) * AS + kk + t4 + 4]);
            }
#pragma unroll
            for (int ni = 0; ni < 4; ni++) {
                int n = ncol0 + ni * 8;
                uint32_t b0 = __float_as_uint(Bsh[(kk + t4) * BS + n + g]);
                uint32_t b1 = __float_as_uint(Bsh[(kk + t4 + 4) * BS + n + g]);
#pragma unroll
                for (int mi = 0; mi < 2; mi++)
                    mma_tf32(c1[mi][ni], a[mi], b0, b1);
            }
        }
        if (kc < 15) {
            float* Asn = As0 + (1 - p) * 64 * AS;
            float* Bsn = Bs0 + (1 - p) * 32 * BS;
#pragma unroll
            for (int i = 0; i < 2; i++) {
                float4 v = ra[i];
                v.x = to_tf32(v.x); v.y = to_tf32(v.y); v.z = to_tf32(v.z); v.w = to_tf32(v.w);
                *(float4*)&Asn[(ar0 + 32 * i) * AS + ac0] = v;
            }
#pragma unroll
            for (int i = 0; i < 4; i++) {
                float4 v = rb[i];
                v.x = to_tf32(v.x); v.y = to_tf32(v.y); v.z = to_tf32(v.z); v.w = to_tf32(v.w);
                *(float4*)&Bsn[(br0 + 8 * i) * BS + bc0] = v;
            }
        }
        __syncthreads();
        p ^= 1;
    }

    // ---- H = tf32(relu(.)*gate) -> SMEM [64m][128k] ----
#pragma unroll
    for (int mi = 0; mi < 2; mi++) {
        int rA = mrow0 + mi * 16 + g;
        float gA = gates[rA], gB = gates[rA + 8];
#pragma unroll
        for (int ni = 0; ni < 4; ni++) {
            int col = ncol0 + ni * 8 + t4 * 2;
            float2 hA, hB;
            hA.x = to_tf32(fmaxf(c1[mi][ni][0], 0.f) * gA);
            hA.y = to_tf32(fmaxf(c1[mi][ni][1], 0.f) * gA);
            hB.x = to_tf32(fmaxf(c1[mi][ni][2], 0.f) * gB);
            hB.y = to_tf32(fmaxf(c1[mi][ni][3], 0.f) * gB);
            *(float2*)&Hsm[rA * HS + col] = hA;
            *(float2*)&Hsm[(rA + 8) * HS + col] = hB;
        }
    }
    __syncthreads();

    // ---- GEMM2: Y[64,512] = H[64,128] * W2[128,512]; 16 chunks = (v, kch) ----
    float c2[2][4][4];
#pragma unroll
    for (int mi = 0; mi < 2; mi++)
#pragma unroll
        for (int ni = 0; ni < 4; ni++)
#pragma unroll
            for (int j = 0; j < 4; j++) c2[mi][ni][j] = 0.f;

    // prefetch chunk 0 (v=0, kch=0)
#pragma unroll
    for (int i = 0; i < 4; i++)
        rb[i] = *(const float4*)(w2e + (size_t)(br0 + 8 * i) * DM + bc0);
    {
        float* Bsh = Bs0;
#pragma unroll
        for (int i = 0; i < 4; i++) {
            float4 v = rb[i];
            v.x = to_tf32(v.x); v.y = to_tf32(v.y); v.z = to_tf32(v.z); v.w = to_tf32(v.w);
            *(float4*)&Bsh[(br0 + 8 * i) * BS + bc0] = v;
        }
    }
    __syncthreads();

    p = 0;
    for (int c = 0; c < 16; c++) {
        int v = c >> 2, kch = c & 3;
        if (c < 15) {
            int vn = (c + 1) >> 2, kn = (c + 1) & 3;
#pragma unroll
            for (int i = 0; i < 4; i++)
                rb[i] = *(const float4*)(w2e + (size_t)(kn * 32 + br0 + 8 * i) * DM +
                                         vn * 128 + bc0);
        }
        float* Bsh = Bs0 + p * 32 * BS;
#pragma unroll
        for (int ks = 0; ks < 4; ks++) {
            int kh = kch * 32 + ks * 8;          // k into H
            int kk = ks * 8;                     // k into staged B
            uint32_t a[2][4];
#pragma unroll
            for (int mi = 0; mi < 2; mi++) {
                int m = mrow0 + mi * 16;
                a[mi][0] = __float_as_uint(Hsm[(m + g) * HS + kh + t4]);
                a[mi][1] = __float_as_uint(Hsm[(m + g + 8) * HS + kh + t4]);
                a[mi][2] = __float_as_uint(Hsm[(m + g) * HS + kh + t4 + 4]);
                a[mi][3] = __float_as_uint(Hsm[(m + g + 8) * HS + kh + t4 + 4]);
            }
#pragma unroll
            for (int ni = 0; ni < 4; ni++) {
                int n = ncol0 + ni * 8;
                uint32_t b0 = __float_as_uint(Bsh[(kk + t4) * BS + n + g]);
                uint32_t b1 = __float_as_uint(Bsh[(kk + t4 + 4) * BS + n + g]);
#pragma unroll
                for (int mi = 0; mi < 2; mi++)
                    mma_tf32(c2[mi][ni], a[mi], b0, b1);
            }
        }
        if (c < 15) {
            float* Bsn = Bs0 + (1 - p) * 32 * BS;
#pragma unroll
            for (int i = 0; i < 4; i++) {
                float4 w = rb[i];
                w.x = to_tf32(w.x); w.y = to_tf32(w.y); w.z = to_tf32(w.z); w.w = to_tf32(w.w);
                *(float4*)&Bsn[(br0 + 8 * i) * BS + bc0] = w;
            }
        }
        __syncthreads();
        p ^= 1;

        if (kch == 3) {
            int v0 = v * 128;
#pragma unroll
            for (int mi = 0; mi < 2; mi++) {
                int rA = mrow0 + mi * 16 + g;
                int rB = rA + 8;
#pragma unroll
                for (int ni = 0; ni < 4; ni++) {
                    int col = v0 + ncol0 + ni * 8 + t4 * 2;
                    if (rA < cnt) {
                        float2 o0; o0.x = c2[mi][ni][0]; o0.y = c2[mi][ni][1];
                        *(float2*)(g_buf + (size_t)nks[rA] * DM + col) = o0;
                    }
                    if (rB < cnt) {
                        float2 o1; o1.x = c2[mi][ni][2]; o1.y = c2[mi][ni][3];
                        *(float2*)(g_buf + (size_t)nks[rB] * DM + col) = o1;
                    }
                    c2[mi][ni][0] = 0.f; c2[mi][ni][1] = 0.f;
                    c2[mi][ni][2] = 0.f; c2[mi][ni][3] = 0.f;
                }
            }
        }
    }

    // ---- fused reduce: last block to complete a token sums its 4 partials ----
    __syncthreads();
    __threadfence();                       // release our g_buf stores
    if (tid < cnt) {
        int n = nrow[tid];
        int old = atomicAdd(&g_tokcnt[n], 1);
        if (old == 3) {
            int w = atomicAdd(&nwin, 1);
            winners[w] = n;
        }
    }
    __syncthreads();
    __threadfence();                       // acquire other blocks' g_buf stores
    int nw = nwin;
    const float4* bb = (const float4*)g_buf;
    for (int i = tid; i < nw * 128; i += 256) {
        int n = winners[i >> 7], v4 = i & 127;
        size_t b0 = (size_t)(n * 4) * 128 + v4;
        float4 r0 = bb[b0];
        float4 r1 = bb[b0 + 128];
        float4 r2 = bb[b0 + 256];
        float4 r3 = bb[b0 + 384];
        float4 o;
        o.x = (r0.x + r1.x) + (r2.x + r3.x);
        o.y = (r0.y + r1.y) + (r2.y + r3.y);
        o.z = (r0.z + r1.z) + (r2.z + r3.z);
        o.w = (r0.w + r1.w) + (r2.w + r3.w);
        ((float4*)y)[(size_t)n * 128 + v4] = o;
    }
}

extern "C" void kernel_launch(void* const* d_in, const int* in_sizes, int n_in,
                              void* d_out, int out_size) {
    const float* x   = (const float*)d_in[0];
    const float* sel = (const float*)d_in[1];
    const float* w1  = (const float*)d_in[2];
    const float* w2  = (const float*)d_in[3];
    float* y = (float*)d_out;

    cudaFuncSetAttribute(k_expert, cudaFuncAttributeMaxDynamicSharedMemorySize, SMEM_EXPERT);

    k_score<<<NBLK, 256>>>(x, sel);
    k_scan<<<1, 32>>>();
    k_fill<<<NBLK, 128>>>();
    k_expert<<<dim3(16, EX), 256, SMEM_EXPERT>>>(x, w1, w2, y);
}